// round 4
// baseline (speedup 1.0000x reference)
#include <cuda_runtime.h>
#include <cuda_bf16.h>
#include <cstdint>

// ---------------- problem constants ----------------
#define DHD   32
#define SCALE 0.1767766952966369f   // 32^-0.5

// ---------------- smem layout (bytes) ----------------
#define STRA  136                    // bf16 row stride of A tiles (272 B)
#define STRQ  132                    // fp32 row stride of Q/K/V/PO (528 B, 16B-aligned)
#define SA_H  0
#define SA_L  17408
#define SW_H  34816                  // W stage: 128 rows x 272 B (hi)
#define SW_L  69632
#define SQKV  104448                 // Q / K / V fp32, each 64*132*4 = 33792 B
#define QKV_SZ 33792
#define SMEM_BYTES (SQKV + 3 * QKV_SZ)   // 205824

// ---------------- ptx helpers ----------------
__device__ __forceinline__ uint32_t smem_u32(const void* p) {
    uint32_t a;
    asm("{ .reg .u64 t; cvta.to.shared.u64 t, %1; cvt.u32.u64 %0, t; }" : "=r"(a) : "l"(p));
    return a;
}
__device__ __forceinline__ void ldsm4(uint32_t* r, uint32_t addr) {
    asm volatile("ldmatrix.sync.aligned.m8n8.x4.shared.b16 {%0,%1,%2,%3}, [%4];"
                 : "=r"(r[0]), "=r"(r[1]), "=r"(r[2]), "=r"(r[3]) : "r"(addr));
}
__device__ __forceinline__ void mma16816(float* c, const uint32_t* a,
                                         uint32_t b0, uint32_t b1) {
    asm volatile(
        "mma.sync.aligned.m16n8k16.row.col.f32.bf16.bf16.f32 "
        "{%0,%1,%2,%3}, {%4,%5,%6,%7}, {%8,%9}, {%0,%1,%2,%3};"
        : "+f"(c[0]), "+f"(c[1]), "+f"(c[2]), "+f"(c[3])
        : "r"(a[0]), "r"(a[1]), "r"(a[2]), "r"(a[3]), "r"(b0), "r"(b1));
}

// ---------------- packed f32x2 (FFMA2) helpers ----------------
__device__ __forceinline__ unsigned long long pk2(float x, float y) {
    unsigned long long r;
    asm("mov.b64 %0, {%1,%2};" : "=l"(r) : "f"(x), "f"(y));
    return r;
}
__device__ __forceinline__ void upk2(unsigned long long v, float& x, float& y) {
    asm("mov.b64 {%0,%1}, %2;" : "=f"(x), "=f"(y) : "l"(v));
}
__device__ __forceinline__ unsigned long long ffma2(unsigned long long a,
                                                    unsigned long long b,
                                                    unsigned long long c) {
    unsigned long long d;
    asm("fma.rn.f32x2 %0, %1, %2, %3;" : "=l"(d) : "l"(a), "l"(b), "l"(c));
    return d;
}

// ---------------- persistent transposed/split weights ----------------
__device__ __nv_bfloat16 g_wqkvT_h[384 * 128];   // [n][k] row-major
__device__ __nv_bfloat16 g_wqkvT_l[384 * 128];
__device__ __nv_bfloat16 g_wprojT_h[128 * 128];
__device__ __nv_bfloat16 g_wprojT_l[128 * 128];

__global__ void init_weights_kernel(const float* __restrict__ wqkv,
                                    const float* __restrict__ wproj) {
    int t = blockIdx.x * blockDim.x + threadIdx.x;   // 65536
    if (t < 49152) {
        int n = t >> 7, k = t & 127;
        float v = wqkv[k * 384 + n];
        __nv_bfloat16 h = __float2bfloat16(v);
        g_wqkvT_h[n * 128 + k] = h;
        g_wqkvT_l[n * 128 + k] = __float2bfloat16(v - __bfloat162float(h));
    } else {
        int r = t - 49152;
        int n = r >> 7, k = r & 127;
        float v = wproj[k * 128 + n];
        __nv_bfloat16 h = __float2bfloat16(v);
        g_wprojT_h[n * 128 + k] = h;
        g_wprojT_l[n * 128 + k] = __float2bfloat16(v - __bfloat162float(h));
    }
}

// ---------------- main kernel: 1 window per CTA, 512 threads ----------------
__global__ __launch_bounds__(512, 1)
void swin_mma_kernel(const float* __restrict__ x,
                     const float* __restrict__ bproj,
                     float* __restrict__ out) {
    extern __shared__ char smem[];
    const uint32_t sb = smem_u32(smem);
    const int tid  = threadIdx.x;
    const int wid  = tid >> 5;
    const int lane = tid & 31;

    const int bid = blockIdx.x;
    const int b   = bid >> 10;
    const int wh  = (bid >> 5) & 31;
    const int ww  = bid & 31;

    // gather/scatter mapping: 512 threads, 64 tokens x 8 channel-stripes
    const int l8   = tid & 63;
    const int rr   = l8 >> 3, cc8 = l8 & 7;
    const int cpar = tid >> 6;                 // 0..7
    const int gh   = (wh * 8 + rr + 4) & 255;
    const int gw   = (ww * 8 + cc8 + 4) & 255;
    const size_t gbase = (size_t)b * (128u * 65536u) + (size_t)gh * 256 + (size_t)gw;

    __nv_bfloat16* Ah = (__nv_bfloat16*)(smem + SA_H);
    __nv_bfloat16* Al = (__nv_bfloat16*)(smem + SA_L);

    // ---- Phase 1: gather + fp32 -> bf16 hi/lo split into A tile ----
    #pragma unroll 4
    for (int it = 0; it < 16; ++it) {
        int ch = cpar + it * 8;
        float v = x[gbase + (size_t)ch * 65536u];
        __nv_bfloat16 h = __float2bfloat16(v);
        Ah[l8 * STRA + ch] = h;
        Al[l8 * STRA + ch] = __float2bfloat16(v - __bfloat162float(h));
    }
    __syncthreads();

    // warp tiling: 4 (M) x 4 (N) warps; warp tile 16x32; N-chunk = 128
    const int m0 = (wid >> 2) * 16;
    const int nb = (wid & 3) * 32;
    const int gid = lane >> 2, tig = lane & 3;

    const uint32_t aOffBase =
        (uint32_t)((m0 + ((lane >> 3) & 1) * 8 + (lane & 7)) * 272 + ((lane >> 4) * 8) * 2);
    const uint32_t bRowOff = (uint32_t)((((lane >> 4) & 1) * 8 + (lane & 7)) * 272);
    const uint32_t bKOff   = (uint32_t)(((lane >> 3) & 1) * 16);

    // ---- Phase 2: QKV GEMM, 3 chunks of N=128, 3-pass bf16 split ----
    for (int ch = 0; ch < 3; ++ch) {
        {
            const uint4* srcH = (const uint4*)(g_wqkvT_h + (size_t)ch * 128 * 128);
            const uint4* srcL = (const uint4*)(g_wqkvT_l + (size_t)ch * 128 * 128);
            #pragma unroll
            for (int i = 0; i < 4; ++i) {
                int idx = tid + i * 512;                  // 0..2047
                int row = idx >> 4, col = idx & 15;
                *(uint4*)(smem + SW_H + row * 272 + col * 16) = srcH[idx];
                *(uint4*)(smem + SW_L + row * 272 + col * 16) = srcL[idx];
            }
        }
        __syncthreads();

        float acc[4][4];
        #pragma unroll
        for (int j = 0; j < 4; ++j)
            #pragma unroll
            for (int q = 0; q < 4; ++q) acc[j][q] = 0.f;

        #pragma unroll
        for (int kk = 0; kk < 8; ++kk) {
            const uint32_t ka = kk * 32;
            uint32_t ah[4], al[4], bh[2][4], bl[2][4];
            ldsm4(ah, sb + SA_H + aOffBase + ka);
            ldsm4(al, sb + SA_L + aOffBase + ka);
            #pragma unroll
            for (int g = 0; g < 2; ++g) {
                uint32_t ro = (uint32_t)((nb + g * 16) * 272) + bRowOff + bKOff + ka;
                ldsm4(bh[g], sb + SW_H + ro);
                ldsm4(bl[g], sb + SW_L + ro);
            }
            #pragma unroll
            for (int j = 0; j < 4; ++j) {
                const int g = j >> 1, e = (j & 1) * 2;
                mma16816(acc[j], ah, bh[g][e], bh[g][e + 1]);
                mma16816(acc[j], ah, bl[g][e], bl[g][e + 1]);
                mma16816(acc[j], al, bh[g][e], bh[g][e + 1]);
            }
        }

        // chunk ch IS matrix ch (Q/K/V): store C tile fp32
        {
            float* D = (float*)(smem + SQKV + ch * QKV_SZ);
            #pragma unroll
            for (int j = 0; j < 4; ++j) {
                int ccol = nb + j * 8 + 2 * tig;
                *(float2*)&D[(m0 + gid) * STRQ + ccol]     = make_float2(acc[j][0], acc[j][1]);
                *(float2*)&D[(m0 + gid + 8) * STRQ + ccol] = make_float2(acc[j][2], acc[j][3]);
            }
        }
        __syncthreads();
    }

    // ---- stage proj weights now (overlaps with attention phase) ----
    {
        const uint4* srcH = (const uint4*)g_wprojT_h;
        const uint4* srcL = (const uint4*)g_wprojT_l;
        #pragma unroll
        for (int i = 0; i < 4; ++i) {
            int idx = tid + i * 512;
            int row = idx >> 4, col = idx & 15;
            *(uint4*)(smem + SW_H + row * 272 + col * 16) = srcH[idx];
            *(uint4*)(smem + SW_L + row * 272 + col * 16) = srcL[idx];
        }
    }

    // ---- Phase 3: attention, split-key (2 threads per (head,row)) ----
    {
        const float* Qs = (const float*)(smem + SQKV);
        const float* Ks = (const float*)(smem + SQKV + QKV_SZ);
        const float* Vs = (const float*)(smem + SQKV + 2 * QKV_SZ);
        const int p    = tid >> 1;       // 0..255
        const int hh   = p >> 6;         // head
        const int l    = p & 63;         // query row
        const int half = tid & 1;        // key parity

        // q row (unscaled; SCALE folded into exp arg). LDS.128 loads.
        unsigned long long q2[16];
        {
            const float* qrow = &Qs[l * STRQ + hh * DHD];
            #pragma unroll
            for (int i = 0; i < 8; ++i) {
                ulonglong2 qv = *(const ulonglong2*)&qrow[4 * i];
                q2[2 * i]     = qv.x;
                q2[2 * i + 1] = qv.y;
            }
        }

        // S over 32 keys (parity-interleaved -> conflict-free dual broadcast)
        float s[32];
        #pragma unroll
        for (int m = 0; m < 32; ++m) {
            const float* kr = &Ks[(2 * m + half) * STRQ + hh * DHD];
            unsigned long long a = 0ull;
            #pragma unroll
            for (int i = 0; i < 8; ++i) {
                ulonglong2 kv = *(const ulonglong2*)&kr[4 * i];
                a = ffma2(q2[2 * i], kv.x, a);
                a = ffma2(q2[2 * i + 1], kv.y, a);
            }
            float ax, ay; upk2(a, ax, ay);
            s[m] = ax + ay;
        }

        // local softmax (unnormalized)
        float mx = -1e30f;
        #pragma unroll
        for (int m = 0; m < 32; ++m) mx = fmaxf(mx, s[m]);
        float sum = 0.f;
        #pragma unroll
        for (int m = 0; m < 32; ++m) {
            float e = __expf((s[m] - mx) * SCALE);
            s[m] = e; sum += e;
        }

        // partial O
        unsigned long long o2[16];
        #pragma unroll
        for (int d2 = 0; d2 < 16; ++d2) o2[d2] = 0ull;
        #pragma unroll
        for (int m = 0; m < 32; ++m) {
            unsigned long long p2 = pk2(s[m], s[m]);
            const float* vr = &Vs[(2 * m + half) * STRQ + hh * DHD];
            #pragma unroll
            for (int i = 0; i < 8; ++i) {
                ulonglong2 vv = *(const ulonglong2*)&vr[4 * i];
                o2[2 * i]     = ffma2(p2, vv.x, o2[2 * i]);
                o2[2 * i + 1] = ffma2(p2, vv.y, o2[2 * i + 1]);
            }
        }

        // combine across the lane pair
        const unsigned FULL = 0xffffffffu;
        float mxo = __shfl_xor_sync(FULL, mx, 1);
        float M   = fmaxf(mx, mxo);
        float f   = __expf((mx - M) * SCALE);
        float sc  = sum * f;
        float st  = sc + __shfl_xor_sync(FULL, sc, 1);
        float inv = 1.0f / st;

        // each lane of the pair writes half of the 32 output dims
        #pragma unroll
        for (int d2 = 0; d2 < 16; ++d2) {
            float ox, oy; upk2(o2[d2], ox, oy);
            ox *= f; oy *= f;
            ox += __shfl_xor_sync(FULL, ox, 1);
            oy += __shfl_xor_sync(FULL, oy, 1);
            if ((d2 >> 3) == half) {
                ox *= inv; oy *= inv;
                __nv_bfloat16 hx = __float2bfloat16(ox);
                __nv_bfloat16 hy = __float2bfloat16(oy);
                int e = l * STRA + hh * DHD + 2 * d2;
                *(__nv_bfloat162*)(Ah + e) = __halves2bfloat162(hx, hy);
                *(__nv_bfloat162*)(Al + e) = __halves2bfloat162(
                    __float2bfloat16(ox - __bfloat162float(hx)),
                    __float2bfloat16(oy - __bfloat162float(hy)));
            }
        }
    }
    __syncthreads();

    // ---- Phase 4: proj GEMM (single chunk N=128) + bias -> PO (= Q region) ----
    {
        float acc[4][4];
        #pragma unroll
        for (int j = 0; j < 4; ++j)
            #pragma unroll
            for (int q = 0; q < 4; ++q) acc[j][q] = 0.f;

        #pragma unroll
        for (int kk = 0; kk < 8; ++kk) {
            const uint32_t ka = kk * 32;
            uint32_t ah[4], al[4], bh[2][4], bl[2][4];
            ldsm4(ah, sb + SA_H + aOffBase + ka);
            ldsm4(al, sb + SA_L + aOffBase + ka);
            #pragma unroll
            for (int g = 0; g < 2; ++g) {
                uint32_t ro = (uint32_t)((nb + g * 16) * 272) + bRowOff + bKOff + ka;
                ldsm4(bh[g], sb + SW_H + ro);
                ldsm4(bl[g], sb + SW_L + ro);
            }
            #pragma unroll
            for (int j = 0; j < 4; ++j) {
                const int g = j >> 1, e = (j & 1) * 2;
                mma16816(acc[j], ah, bh[g][e], bh[g][e + 1]);
                mma16816(acc[j], ah, bl[g][e], bl[g][e + 1]);
                mma16816(acc[j], al, bh[g][e], bh[g][e + 1]);
            }
        }
        float* PO = (float*)(smem + SQKV);   // Q region dead
        #pragma unroll
        for (int j = 0; j < 4; ++j) {
            int ccol = nb + j * 8 + 2 * tig;
            float b0 = __ldg(&bproj[ccol]), b1 = __ldg(&bproj[ccol + 1]);
            *(float2*)&PO[(m0 + gid) * STRQ + ccol] =
                make_float2(acc[j][0] + b0, acc[j][1] + b1);
            *(float2*)&PO[(m0 + gid + 8) * STRQ + ccol] =
                make_float2(acc[j][2] + b0, acc[j][3] + b1);
        }
    }
    __syncthreads();

    // ---- Phase 5: scatter ----
    {
        const float* PO = (const float*)(smem + SQKV);
        #pragma unroll 4
        for (int it = 0; it < 16; ++it) {
            int ch = cpar + it * 8;
            out[gbase + (size_t)ch * 65536u] = PO[l8 * STRQ + ch];
        }
    }
}

extern "C" void kernel_launch(void* const* d_in, const int* in_sizes, int n_in,
                              void* d_out, int out_size) {
    (void)in_sizes; (void)n_in; (void)out_size;
    const float* x     = (const float*)d_in[0];
    const float* wqkv  = (const float*)d_in[1];
    const float* wproj = (const float*)d_in[2];
    const float* bproj = (const float*)d_in[3];
    float* out = (float*)d_out;

    init_weights_kernel<<<256, 256>>>(wqkv, wproj);

    cudaFuncSetAttribute(swin_mma_kernel,
                         cudaFuncAttributeMaxDynamicSharedMemorySize, SMEM_BYTES);
    swin_mma_kernel<<<8192, 512, SMEM_BYTES>>>(x, bproj, out);
}

// round 5
// speedup vs baseline: 1.1841x; 1.1841x over previous
#include <cuda_runtime.h>
#include <cuda_fp16.h>
#include <cstdint>

// ---------------- problem constants ----------------
#define DHD   32
#define SCALE 0.1767766952966369f   // 32^-0.5

// ---------------- smem layout (bytes) ----------------
#define STRA  136                    // fp16 row stride of A tiles (272 B)
#define STRQ  132                    // fp32 row stride of Q/K/V/PO
#define SA_H  0
#define SA_L  17408
#define SW    34816                  // W stage: 128 rows x 272 B (single fp16)
#define SQKV  69632                  // Q / K / V fp32, each 64*132*4 = 33792 B
#define QKV_SZ 33792
#define SMEM_BYTES (SQKV + 3 * QKV_SZ)   // 171008

// ---------------- ptx helpers ----------------
__device__ __forceinline__ uint32_t smem_u32(const void* p) {
    uint32_t a;
    asm("{ .reg .u64 t; cvta.to.shared.u64 t, %1; cvt.u32.u64 %0, t; }" : "=r"(a) : "l"(p));
    return a;
}
__device__ __forceinline__ void ldsm4(uint32_t* r, uint32_t addr) {
    asm volatile("ldmatrix.sync.aligned.m8n8.x4.shared.b16 {%0,%1,%2,%3}, [%4];"
                 : "=r"(r[0]), "=r"(r[1]), "=r"(r[2]), "=r"(r[3]) : "r"(addr));
}
__device__ __forceinline__ void mma16816(float* c, const uint32_t* a,
                                         uint32_t b0, uint32_t b1) {
    asm volatile(
        "mma.sync.aligned.m16n8k16.row.col.f32.f16.f16.f32 "
        "{%0,%1,%2,%3}, {%4,%5,%6,%7}, {%8,%9}, {%0,%1,%2,%3};"
        : "+f"(c[0]), "+f"(c[1]), "+f"(c[2]), "+f"(c[3])
        : "r"(a[0]), "r"(a[1]), "r"(a[2]), "r"(a[3]), "r"(b0), "r"(b1));
}

// ---------------- packed f32x2 (FFMA2) helpers ----------------
__device__ __forceinline__ unsigned long long pk2(float x, float y) {
    unsigned long long r;
    asm("mov.b64 %0, {%1,%2};" : "=l"(r) : "f"(x), "f"(y));
    return r;
}
__device__ __forceinline__ void upk2(unsigned long long v, float& x, float& y) {
    asm("mov.b64 {%0,%1}, %2;" : "=f"(x), "=f"(y) : "l"(v));
}
__device__ __forceinline__ unsigned long long ffma2(unsigned long long a,
                                                    unsigned long long b,
                                                    unsigned long long c) {
    unsigned long long d;
    asm("fma.rn.f32x2 %0, %1, %2, %3;" : "=l"(d) : "l"(a), "l"(b), "l"(c));
    return d;
}

// ---------------- persistent transposed fp16 weights (single-rounded) ----------
__device__ __half g_wqkvT[384 * 128];   // [n][k] row-major
__device__ __half g_wprojT[128 * 128];

__global__ void init_weights_kernel(const float* __restrict__ wqkv,
                                    const float* __restrict__ wproj) {
    int t = blockIdx.x * blockDim.x + threadIdx.x;   // 65536
    if (t < 49152) {
        int n = t >> 7, k = t & 127;
        g_wqkvT[n * 128 + k] = __float2half_rn(wqkv[k * 384 + n]);
    } else {
        int r = t - 49152;
        int n = r >> 7, k = r & 127;
        g_wprojT[n * 128 + k] = __float2half_rn(wproj[k * 128 + n]);
    }
}

// ---------------- main kernel: 1 window per CTA, 512 threads ----------------
__global__ __launch_bounds__(512, 1)
void swin_mma_kernel(const float* __restrict__ x,
                     const float* __restrict__ bproj,
                     float* __restrict__ out) {
    extern __shared__ char smem[];
    const uint32_t sb = smem_u32(smem);
    const int tid  = threadIdx.x;
    const int wid  = tid >> 5;
    const int lane = tid & 31;

    const int bid = blockIdx.x;
    const int b   = bid >> 10;
    const int wh  = (bid >> 5) & 31;
    const int ww  = bid & 31;

    // gather/scatter mapping: 512 threads, 64 tokens x 8 channel-stripes
    const int l8   = tid & 63;
    const int rr   = l8 >> 3, cc8 = l8 & 7;
    const int cpar = tid >> 6;                 // 0..7
    const int gh   = (wh * 8 + rr + 4) & 255;
    const int gw   = (ww * 8 + cc8 + 4) & 255;
    const size_t gbase = (size_t)b * (128u * 65536u) + (size_t)gh * 256 + (size_t)gw;

    __half* Ah = (__half*)(smem + SA_H);
    __half* Al = (__half*)(smem + SA_L);

    // ---- Phase 1: gather + fp32 -> fp16 hi/lo (exact) split into A tile ----
    #pragma unroll 4
    for (int it = 0; it < 16; ++it) {
        int ch = cpar + it * 8;
        float v = x[gbase + (size_t)ch * 65536u];
        __half h = __float2half_rn(v);
        Ah[l8 * STRA + ch] = h;
        Al[l8 * STRA + ch] = __float2half_rn(v - __half2float(h));
    }
    __syncthreads();

    // warp tiling: 4 (M) x 4 (N) warps; warp tile 16x32; N-chunk = 128
    const int m0 = (wid >> 2) * 16;
    const int nb = (wid & 3) * 32;
    const int gid = lane >> 2, tig = lane & 3;

    const uint32_t aOffBase =
        (uint32_t)((m0 + ((lane >> 3) & 1) * 8 + (lane & 7)) * 272 + ((lane >> 4) * 8) * 2);
    const uint32_t bRowOff = (uint32_t)((((lane >> 4) & 1) * 8 + (lane & 7)) * 272);
    const uint32_t bKOff   = (uint32_t)(((lane >> 3) & 1) * 16);

    // ---- Phase 2: QKV GEMM, 3 chunks of N=128, 2-pass (A-split) fp16 ----
    for (int ch = 0; ch < 3; ++ch) {
        {
            const uint4* src = (const uint4*)(g_wqkvT + (size_t)ch * 128 * 128);
            #pragma unroll
            for (int i = 0; i < 4; ++i) {
                int idx = tid + i * 512;                  // 0..2047
                int row = idx >> 4, col = idx & 15;
                *(uint4*)(smem + SW + row * 272 + col * 16) = src[idx];
            }
        }
        __syncthreads();

        float acc[4][4];
        #pragma unroll
        for (int j = 0; j < 4; ++j)
            #pragma unroll
            for (int q = 0; q < 4; ++q) acc[j][q] = 0.f;

        #pragma unroll
        for (int kk = 0; kk < 8; ++kk) {
            const uint32_t ka = kk * 32;
            uint32_t ah[4], al[4], bb[2][4];
            ldsm4(ah, sb + SA_H + aOffBase + ka);
            ldsm4(al, sb + SA_L + aOffBase + ka);
            #pragma unroll
            for (int g = 0; g < 2; ++g) {
                uint32_t ro = (uint32_t)((nb + g * 16) * 272) + bRowOff + bKOff + ka;
                ldsm4(bb[g], sb + SW + ro);
            }
            #pragma unroll
            for (int j = 0; j < 4; ++j) {
                const int g = j >> 1, e = (j & 1) * 2;
                mma16816(acc[j], ah, bb[g][e], bb[g][e + 1]);
                mma16816(acc[j], al, bb[g][e], bb[g][e + 1]);
            }
        }

        // chunk ch IS matrix ch (Q/K/V): store C tile fp32
        {
            float* D = (float*)(smem + SQKV + ch * QKV_SZ);
            #pragma unroll
            for (int j = 0; j < 4; ++j) {
                int ccol = nb + j * 8 + 2 * tig;
                *(float2*)&D[(m0 + gid) * STRQ + ccol]     = make_float2(acc[j][0], acc[j][1]);
                *(float2*)&D[(m0 + gid + 8) * STRQ + ccol] = make_float2(acc[j][2], acc[j][3]);
            }
        }
        __syncthreads();
    }

    // ---- stage proj weights now (overlaps with attention phase) ----
    {
        const uint4* src = (const uint4*)g_wprojT;
        #pragma unroll
        for (int i = 0; i < 4; ++i) {
            int idx = tid + i * 512;
            int row = idx >> 4, col = idx & 15;
            *(uint4*)(smem + SW + row * 272 + col * 16) = src[idx];
        }
    }

    // ---- Phase 3: attention, split-key (2 threads per (head,row)) ----
    {
        const float* Qs = (const float*)(smem + SQKV);
        const float* Ks = (const float*)(smem + SQKV + QKV_SZ);
        const float* Vs = (const float*)(smem + SQKV + 2 * QKV_SZ);
        const int p    = tid >> 1;       // 0..255
        const int hh   = p >> 6;         // head
        const int l    = p & 63;         // query row
        const int half = tid & 1;        // key parity

        // q row (unscaled; SCALE folded into exp arg). LDS.128 loads.
        unsigned long long q2[16];
        {
            const float* qrow = &Qs[l * STRQ + hh * DHD];
            #pragma unroll
            for (int i = 0; i < 8; ++i) {
                ulonglong2 qv = *(const ulonglong2*)&qrow[4 * i];
                q2[2 * i]     = qv.x;
                q2[2 * i + 1] = qv.y;
            }
        }

        // S over 32 keys (parity-interleaved -> conflict-free dual broadcast)
        float s[32];
        #pragma unroll
        for (int m = 0; m < 32; ++m) {
            const float* kr = &Ks[(2 * m + half) * STRQ + hh * DHD];
            unsigned long long a = 0ull;
            #pragma unroll
            for (int i = 0; i < 8; ++i) {
                ulonglong2 kv = *(const ulonglong2*)&kr[4 * i];
                a = ffma2(q2[2 * i], kv.x, a);
                a = ffma2(q2[2 * i + 1], kv.y, a);
            }
            float ax, ay; upk2(a, ax, ay);
            s[m] = ax + ay;
        }

        // local softmax (unnormalized)
        float mx = -1e30f;
        #pragma unroll
        for (int m = 0; m < 32; ++m) mx = fmaxf(mx, s[m]);
        float sum = 0.f;
        #pragma unroll
        for (int m = 0; m < 32; ++m) {
            float e = __expf((s[m] - mx) * SCALE);
            s[m] = e; sum += e;
        }

        // partial O
        unsigned long long o2[16];
        #pragma unroll
        for (int d2 = 0; d2 < 16; ++d2) o2[d2] = 0ull;
        #pragma unroll
        for (int m = 0; m < 32; ++m) {
            unsigned long long p2 = pk2(s[m], s[m]);
            const float* vr = &Vs[(2 * m + half) * STRQ + hh * DHD];
            #pragma unroll
            for (int i = 0; i < 8; ++i) {
                ulonglong2 vv = *(const ulonglong2*)&vr[4 * i];
                o2[2 * i]     = ffma2(p2, vv.x, o2[2 * i]);
                o2[2 * i + 1] = ffma2(p2, vv.y, o2[2 * i + 1]);
            }
        }

        // combine across the lane pair
        const unsigned FULL = 0xffffffffu;
        float mxo = __shfl_xor_sync(FULL, mx, 1);
        float M   = fmaxf(mx, mxo);
        float f   = __expf((mx - M) * SCALE);
        float sc  = sum * f;
        float st  = sc + __shfl_xor_sync(FULL, sc, 1);
        float inv = 1.0f / st;

        // each lane of the pair writes half of the 32 output dims (fp16 h/l exact split)
        #pragma unroll
        for (int d2 = 0; d2 < 16; ++d2) {
            float ox, oy; upk2(o2[d2], ox, oy);
            ox *= f; oy *= f;
            ox += __shfl_xor_sync(FULL, ox, 1);
            oy += __shfl_xor_sync(FULL, oy, 1);
            if ((d2 >> 3) == half) {
                ox *= inv; oy *= inv;
                __half hx = __float2half_rn(ox);
                __half hy = __float2half_rn(oy);
                int e = l * STRA + hh * DHD + 2 * d2;
                *(__half2*)(Ah + e) = __halves2half2(hx, hy);
                *(__half2*)(Al + e) = __halves2half2(
                    __float2half_rn(ox - __half2float(hx)),
                    __float2half_rn(oy - __half2float(hy)));
            }
        }
    }
    __syncthreads();

    // ---- Phase 4: proj GEMM (single chunk N=128) + bias -> PO (= Q region) ----
    {
        float acc[4][4];
        #pragma unroll
        for (int j = 0; j < 4; ++j)
            #pragma unroll
            for (int q = 0; q < 4; ++q) acc[j][q] = 0.f;

        #pragma unroll
        for (int kk = 0; kk < 8; ++kk) {
            const uint32_t ka = kk * 32;
            uint32_t ah[4], al[4], bb[2][4];
            ldsm4(ah, sb + SA_H + aOffBase + ka);
            ldsm4(al, sb + SA_L + aOffBase + ka);
            #pragma unroll
            for (int g = 0; g < 2; ++g) {
                uint32_t ro = (uint32_t)((nb + g * 16) * 272) + bRowOff + bKOff + ka;
                ldsm4(bb[g], sb + SW + ro);
            }
            #pragma unroll
            for (int j = 0; j < 4; ++j) {
                const int g = j >> 1, e = (j & 1) * 2;
                mma16816(acc[j], ah, bb[g][e], bb[g][e + 1]);
                mma16816(acc[j], al, bb[g][e], bb[g][e + 1]);
            }
        }
        float* PO = (float*)(smem + SQKV);   // Q region dead
        #pragma unroll
        for (int j = 0; j < 4; ++j) {
            int ccol = nb + j * 8 + 2 * tig;
            float b0 = __ldg(&bproj[ccol]), b1 = __ldg(&bproj[ccol + 1]);
            *(float2*)&PO[(m0 + gid) * STRQ + ccol] =
                make_float2(acc[j][0] + b0, acc[j][1] + b1);
            *(float2*)&PO[(m0 + gid + 8) * STRQ + ccol] =
                make_float2(acc[j][2] + b0, acc[j][3] + b1);
        }
    }
    __syncthreads();

    // ---- Phase 5: scatter ----
    {
        const float* PO = (const float*)(smem + SQKV);
        #pragma unroll 4
        for (int it = 0; it < 16; ++it) {
            int ch = cpar + it * 8;
            out[gbase + (size_t)ch * 65536u] = PO[l8 * STRQ + ch];
        }
    }
}

extern "C" void kernel_launch(void* const* d_in, const int* in_sizes, int n_in,
                              void* d_out, int out_size) {
    (void)in_sizes; (void)n_in; (void)out_size;
    const float* x     = (const float*)d_in[0];
    const float* wqkv  = (const float*)d_in[1];
    const float* wproj = (const float*)d_in[2];
    const float* bproj = (const float*)d_in[3];
    float* out = (float*)d_out;

    init_weights_kernel<<<256, 256>>>(wqkv, wproj);

    cudaFuncSetAttribute(swin_mma_kernel,
                         cudaFuncAttributeMaxDynamicSharedMemorySize, SMEM_BYTES);
    swin_mma_kernel<<<8192, 512, SMEM_BYTES>>>(x, bproj, out);
}

// round 6
// speedup vs baseline: 1.7346x; 1.4648x over previous
#include <cuda_runtime.h>
#include <cuda_fp16.h>
#include <cstdint>

// ---------------- problem constants ----------------
#define SCALE 0.1767766952966369f   // 32^-0.5

// ---------------- smem layout (bytes) ----------------
#define STRA   136                   // fp16 row stride (272 B) for all h/l tiles
#define SA_H   0
#define SA_L   17408
#define SW     34816                 // W stage [128][136] fp16 (34816 B)
#define SQKV0  69632                 // Q tile (h at +0, l at +17408); K at +34816; V at +69632
#define TILE   34816
#define HHALF  17408
#define SPO    69632                 // proj-out fp32 [64][132] overlays Q tile region
#define STRQ   132
#define SMEM_BYTES 174080

// ---------------- ptx helpers ----------------
__device__ __forceinline__ uint32_t smem_u32(const void* p) {
    uint32_t a;
    asm("{ .reg .u64 t; cvta.to.shared.u64 t, %1; cvt.u32.u64 %0, t; }" : "=r"(a) : "l"(p));
    return a;
}
__device__ __forceinline__ void ldsm4(uint32_t* r, uint32_t addr) {
    asm volatile("ldmatrix.sync.aligned.m8n8.x4.shared.b16 {%0,%1,%2,%3}, [%4];"
                 : "=r"(r[0]), "=r"(r[1]), "=r"(r[2]), "=r"(r[3]) : "r"(addr));
}
__device__ __forceinline__ void ldsm4t(uint32_t* r, uint32_t addr) {
    asm volatile("ldmatrix.sync.aligned.m8n8.x4.trans.shared.b16 {%0,%1,%2,%3}, [%4];"
                 : "=r"(r[0]), "=r"(r[1]), "=r"(r[2]), "=r"(r[3]) : "r"(addr));
}
__device__ __forceinline__ void mma16816(float* c, const uint32_t* a,
                                         uint32_t b0, uint32_t b1) {
    asm volatile(
        "mma.sync.aligned.m16n8k16.row.col.f32.f16.f16.f32 "
        "{%0,%1,%2,%3}, {%4,%5,%6,%7}, {%8,%9}, {%0,%1,%2,%3};"
        : "+f"(c[0]), "+f"(c[1]), "+f"(c[2]), "+f"(c[3])
        : "r"(a[0]), "r"(a[1]), "r"(a[2]), "r"(a[3]), "r"(b0), "r"(b1));
}
// exact fp32 -> fp16 hi/lo split of a pair, packed as half2 words
__device__ __forceinline__ void split2(float x, float y, uint32_t& h, uint32_t& l) {
    __half hx = __float2half_rn(x), hy = __float2half_rn(y);
    __half2 H = __halves2half2(hx, hy);
    __half2 L = __halves2half2(__float2half_rn(x - __half2float(hx)),
                               __float2half_rn(y - __half2float(hy)));
    h = *(uint32_t*)&H;
    l = *(uint32_t*)&L;
}

// ---------------- persistent transposed fp16 weights (single-rounded) ----------
__device__ __half g_wqkvT[384 * 128];   // [n][k] row-major
__device__ __half g_wprojT[128 * 128];

__global__ void init_weights_kernel(const float* __restrict__ wqkv,
                                    const float* __restrict__ wproj) {
    int t = blockIdx.x * blockDim.x + threadIdx.x;   // 65536
    if (t < 49152) {
        int n = t >> 7, k = t & 127;
        g_wqkvT[n * 128 + k] = __float2half_rn(wqkv[k * 384 + n]);
    } else {
        int r = t - 49152;
        int n = r >> 7, k = r & 127;
        g_wprojT[n * 128 + k] = __float2half_rn(wproj[k * 128 + n]);
    }
}

// ---------------- main kernel: 1 window per CTA, 512 threads ----------------
__global__ __launch_bounds__(512, 1)
void swin_mma_kernel(const float* __restrict__ x,
                     const float* __restrict__ bproj,
                     float* __restrict__ out) {
    extern __shared__ char smem[];
    const uint32_t sb = smem_u32(smem);
    const int tid  = threadIdx.x;
    const int wid  = tid >> 5;
    const int lane = tid & 31;

    const int bid = blockIdx.x;
    const int b   = bid >> 10;
    const int wh  = (bid >> 5) & 31;
    const int ww  = bid & 31;

    // gather/scatter mapping
    const int l8   = tid & 63;
    const int rr   = l8 >> 3, cc8 = l8 & 7;
    const int cpar = tid >> 6;                 // 0..7
    const int gh   = (wh * 8 + rr + 4) & 255;
    const int gw   = (ww * 8 + cc8 + 4) & 255;
    const size_t gbase = (size_t)b * (128u * 65536u) + (size_t)gh * 256 + (size_t)gw;

    __half* Ah = (__half*)(smem + SA_H);
    __half* Al = (__half*)(smem + SA_L);

    // ---- Phase 1: gather + fp32 -> fp16 hi/lo (exact) split into A tile ----
    #pragma unroll 4
    for (int it = 0; it < 16; ++it) {
        int ch = cpar + it * 8;
        float v = x[gbase + (size_t)ch * 65536u];
        __half h = __float2half_rn(v);
        Ah[l8 * STRA + ch] = h;
        Al[l8 * STRA + ch] = __float2half_rn(v - __half2float(h));
    }
    __syncthreads();

    // GEMM warp tiling: 4 (M) x 4 (N) warps; warp tile 16x32
    const int m0 = (wid >> 2) * 16;
    const int nb = (wid & 3) * 32;
    const int gid = lane >> 2, tig = lane & 3;

    const uint32_t aOffBase =
        (uint32_t)((m0 + ((lane >> 3) & 1) * 8 + (lane & 7)) * 272 + (lane >> 4) * 16);
    const uint32_t bRowOff = (uint32_t)((((lane >> 4) & 1) * 8 + (lane & 7)) * 272);
    const uint32_t bKOff   = (uint32_t)(((lane >> 3) & 1) * 16);

    // ---- Phase 2: QKV GEMM, 3 chunks of N=128 (chunk == Q/K/V), 2-pass fp16 ----
    for (int ch = 0; ch < 3; ++ch) {
        {
            const uint4* src = (const uint4*)(g_wqkvT + (size_t)ch * 128 * 128);
            #pragma unroll
            for (int i = 0; i < 4; ++i) {
                int idx = tid + i * 512;
                int row = idx >> 4, col = idx & 15;
                *(uint4*)(smem + SW + row * 272 + col * 16) = src[idx];
            }
        }
        __syncthreads();

        float acc[4][4];
        #pragma unroll
        for (int j = 0; j < 4; ++j)
            #pragma unroll
            for (int q = 0; q < 4; ++q) acc[j][q] = 0.f;

        #pragma unroll
        for (int kk = 0; kk < 8; ++kk) {
            const uint32_t ka = kk * 32;
            uint32_t ah[4], al[4], bb[2][4];
            ldsm4(ah, sb + SA_H + aOffBase + ka);
            ldsm4(al, sb + SA_L + aOffBase + ka);
            #pragma unroll
            for (int g = 0; g < 2; ++g) {
                uint32_t ro = (uint32_t)((nb + g * 16) * 272) + bRowOff + bKOff + ka;
                ldsm4(bb[g], sb + SW + ro);
            }
            #pragma unroll
            for (int j = 0; j < 4; ++j) {
                const int g = j >> 1, e = (j & 1) * 2;
                mma16816(acc[j], ah, bb[g][e], bb[g][e + 1]);
                mma16816(acc[j], al, bb[g][e], bb[g][e + 1]);
            }
        }

        // store as fp16 hi/lo tile (exact split)
        {
            __half* Th = (__half*)(smem + SQKV0 + ch * TILE);
            __half* Tl = Th + (HHALF / 2);
            #pragma unroll
            for (int j = 0; j < 4; ++j) {
                int ccol = nb + j * 8 + 2 * tig;
                uint32_t h0, l0, h1, l1;
                split2(acc[j][0], acc[j][1], h0, l0);
                split2(acc[j][2], acc[j][3], h1, l1);
                *(uint32_t*)&Th[(m0 + gid) * STRA + ccol]     = h0;
                *(uint32_t*)&Tl[(m0 + gid) * STRA + ccol]     = l0;
                *(uint32_t*)&Th[(m0 + gid + 8) * STRA + ccol] = h1;
                *(uint32_t*)&Tl[(m0 + gid + 8) * STRA + ccol] = l1;
            }
        }
        __syncthreads();
    }

    // ---- stage proj weights (overlaps with attention phase) ----
    {
        const uint4* src = (const uint4*)g_wprojT;
        #pragma unroll
        for (int i = 0; i < 4; ++i) {
            int idx = tid + i * 512;
            int row = idx >> 4, col = idx & 15;
            *(uint4*)(smem + SW + row * 272 + col * 16) = src[idx];
        }
    }

    // ---- Phase 3: attention via MMA. warp -> (head, 16 query rows) ----
    {
        const int head = wid >> 2;
        const int mrow = (wid & 3) * 16;
        const uint32_t sbQh = sb + SQKV0,            sbQl = sbQh + HHALF;
        const uint32_t sbKh = sb + SQKV0 + TILE,     sbKl = sbKh + HHALF;
        const uint32_t sbVh = sb + SQKV0 + 2 * TILE, sbVl = sbVh + HHALF;

        const uint32_t aQ =
            (uint32_t)((mrow + ((lane >> 3) & 1) * 8 + (lane & 7)) * 272 +
                       (lane >> 4) * 16 + head * 64);

        // S = Q K^T (3-pass exact): sacc[j] covers key cols 8j..8j+7
        float sacc[8][4];
        #pragma unroll
        for (int j = 0; j < 8; ++j)
            #pragma unroll
            for (int q = 0; q < 4; ++q) sacc[j][q] = 0.f;

        #pragma unroll
        for (int kk = 0; kk < 2; ++kk) {
            const uint32_t ka = kk * 32;
            uint32_t qh[4], ql[4], kh[4][4], kl[4][4];
            ldsm4(qh, sbQh + aQ + ka);
            ldsm4(ql, sbQl + aQ + ka);
            #pragma unroll
            for (int g = 0; g < 4; ++g) {
                uint32_t ro = (uint32_t)(g * 16 * 272) + bRowOff + bKOff +
                              (uint32_t)(head * 64) + ka;
                ldsm4(kh[g], sbKh + ro);
                ldsm4(kl[g], sbKl + ro);
            }
            #pragma unroll
            for (int j = 0; j < 8; ++j) {
                const int g = j >> 1, e = (j & 1) * 2;
                mma16816(sacc[j], qh, kh[g][e], kh[g][e + 1]);
                mma16816(sacc[j], qh, kl[g][e], kl[g][e + 1]);
                mma16816(sacc[j], ql, kh[g][e], kh[g][e + 1]);
            }
        }

        // softmax over 64 keys; rows (mrow+gid) [c0,c1] and (mrow+gid+8) [c2,c3]
        const unsigned FULL = 0xffffffffu;
        float mx0 = -1e30f, mx1 = -1e30f;
        #pragma unroll
        for (int j = 0; j < 8; ++j) {
            mx0 = fmaxf(mx0, fmaxf(sacc[j][0], sacc[j][1]));
            mx1 = fmaxf(mx1, fmaxf(sacc[j][2], sacc[j][3]));
        }
        mx0 = fmaxf(mx0, __shfl_xor_sync(FULL, mx0, 1));
        mx0 = fmaxf(mx0, __shfl_xor_sync(FULL, mx0, 2));
        mx1 = fmaxf(mx1, __shfl_xor_sync(FULL, mx1, 1));
        mx1 = fmaxf(mx1, __shfl_xor_sync(FULL, mx1, 2));
        float sum0 = 0.f, sum1 = 0.f;
        #pragma unroll
        for (int j = 0; j < 8; ++j) {
            float e0 = __expf((sacc[j][0] - mx0) * SCALE);
            float e1 = __expf((sacc[j][1] - mx0) * SCALE);
            float e2 = __expf((sacc[j][2] - mx1) * SCALE);
            float e3 = __expf((sacc[j][3] - mx1) * SCALE);
            sacc[j][0] = e0; sacc[j][1] = e1; sacc[j][2] = e2; sacc[j][3] = e3;
            sum0 += e0 + e1; sum1 += e2 + e3;
        }
        sum0 += __shfl_xor_sync(FULL, sum0, 1);
        sum0 += __shfl_xor_sync(FULL, sum0, 2);
        sum1 += __shfl_xor_sync(FULL, sum1, 1);
        sum1 += __shfl_xor_sync(FULL, sum1, 2);
        const float inv0 = 1.0f / sum0, inv1 = 1.0f / sum1;

        // O = P V (3-pass exact; P from S accumulators, V via ldmatrix.trans)
        float oacc[4][4];
        #pragma unroll
        for (int j = 0; j < 4; ++j)
            #pragma unroll
            for (int q = 0; q < 4; ++q) oacc[j][q] = 0.f;

        const uint32_t vBase =
            (uint32_t)((((lane >> 3) & 1) * 8 + (lane & 7)) * 272 +
                       (head * 32 + (lane >> 4) * 8) * 2);

        #pragma unroll
        for (int t = 0; t < 4; ++t) {
            uint32_t ph[4], pl[4];
            split2(sacc[2 * t][0],     sacc[2 * t][1],     ph[0], pl[0]);
            split2(sacc[2 * t][2],     sacc[2 * t][3],     ph[1], pl[1]);
            split2(sacc[2 * t + 1][0], sacc[2 * t + 1][1], ph[2], pl[2]);
            split2(sacc[2 * t + 1][2], sacc[2 * t + 1][3], ph[3], pl[3]);
            uint32_t vh[2][4], vl[2][4];
            #pragma unroll
            for (int g = 0; g < 2; ++g) {
                uint32_t ro = vBase + (uint32_t)(t * 16 * 272) + (uint32_t)(g * 32);
                ldsm4t(vh[g], sbVh + ro);
                ldsm4t(vl[g], sbVl + ro);
            }
            #pragma unroll
            for (int j = 0; j < 4; ++j) {
                const int g = j >> 1, e = (j & 1) * 2;
                mma16816(oacc[j], ph, vh[g][e], vh[g][e + 1]);
                mma16816(oacc[j], ph, vl[g][e], vl[g][e + 1]);
                mma16816(oacc[j], pl, vh[g][e], vh[g][e + 1]);
            }
        }

        // normalize + exact split into A' tile
        #pragma unroll
        for (int j = 0; j < 4; ++j) {
            int ccol = head * 32 + j * 8 + 2 * tig;
            uint32_t h0, l0, h1, l1;
            split2(oacc[j][0] * inv0, oacc[j][1] * inv0, h0, l0);
            split2(oacc[j][2] * inv1, oacc[j][3] * inv1, h1, l1);
            *(uint32_t*)&Ah[(mrow + gid) * STRA + ccol]     = h0;
            *(uint32_t*)&Al[(mrow + gid) * STRA + ccol]     = l0;
            *(uint32_t*)&Ah[(mrow + gid + 8) * STRA + ccol] = h1;
            *(uint32_t*)&Al[(mrow + gid + 8) * STRA + ccol] = l1;
        }
    }
    __syncthreads();

    // ---- Phase 4: proj GEMM (N=128) + bias -> PO (overlays Q tile) ----
    {
        float acc[4][4];
        #pragma unroll
        for (int j = 0; j < 4; ++j)
            #pragma unroll
            for (int q = 0; q < 4; ++q) acc[j][q] = 0.f;

        #pragma unroll
        for (int kk = 0; kk < 8; ++kk) {
            const uint32_t ka = kk * 32;
            uint32_t ah[4], al[4], bb[2][4];
            ldsm4(ah, sb + SA_H + aOffBase + ka);
            ldsm4(al, sb + SA_L + aOffBase + ka);
            #pragma unroll
            for (int g = 0; g < 2; ++g) {
                uint32_t ro = (uint32_t)((nb + g * 16) * 272) + bRowOff + bKOff + ka;
                ldsm4(bb[g], sb + SW + ro);
            }
            #pragma unroll
            for (int j = 0; j < 4; ++j) {
                const int g = j >> 1, e = (j & 1) * 2;
                mma16816(acc[j], ah, bb[g][e], bb[g][e + 1]);
                mma16816(acc[j], al, bb[g][e], bb[g][e + 1]);
            }
        }
        float* PO = (float*)(smem + SPO);
        #pragma unroll
        for (int j = 0; j < 4; ++j) {
            int ccol = nb + j * 8 + 2 * tig;
            float b0 = __ldg(&bproj[ccol]), b1 = __ldg(&bproj[ccol + 1]);
            *(float2*)&PO[(m0 + gid) * STRQ + ccol] =
                make_float2(acc[j][0] + b0, acc[j][1] + b1);
            *(float2*)&PO[(m0 + gid + 8) * STRQ + ccol] =
                make_float2(acc[j][2] + b0, acc[j][3] + b1);
        }
    }
    __syncthreads();

    // ---- Phase 5: scatter ----
    {
        const float* PO = (const float*)(smem + SPO);
        #pragma unroll 4
        for (int it = 0; it < 16; ++it) {
            int ch = cpar + it * 8;
            out[gbase + (size_t)ch * 65536u] = PO[l8 * STRQ + ch];
        }
    }
}

extern "C" void kernel_launch(void* const* d_in, const int* in_sizes, int n_in,
                              void* d_out, int out_size) {
    (void)in_sizes; (void)n_in; (void)out_size;
    const float* x     = (const float*)d_in[0];
    const float* wqkv  = (const float*)d_in[1];
    const float* wproj = (const float*)d_in[2];
    const float* bproj = (const float*)d_in[3];
    float* out = (float*)d_out;

    init_weights_kernel<<<256, 256>>>(wqkv, wproj);

    cudaFuncSetAttribute(swin_mma_kernel,
                         cudaFuncAttributeMaxDynamicSharedMemorySize, SMEM_BYTES);
    swin_mma_kernel<<<8192, 512, SMEM_BYTES>>>(x, bproj, out);
}

// round 7
// speedup vs baseline: 1.9621x; 1.1312x over previous
#include <cuda_runtime.h>
#include <cuda_fp16.h>
#include <cstdint>

// ---------------- problem constants ----------------
#define SCALE 0.1767766952966369f   // 32^-0.5

// ---------------- smem layout (bytes) ----------------
#define STRA 136                     // fp16 row stride (272 B)
#define SA_H 0
#define SA_L 17408
#define SK_H 34816
#define SK_L 52224
#define SV_H 69632
#define SV_L 87040
#define SPO  34816                   // proj-out fp32 [64][132] overlays K tile
#define STRQ 132
#define SMEM_BYTES 104448

// ---------------- ptx helpers ----------------
__device__ __forceinline__ uint32_t smem_u32(const void* p) {
    uint32_t a;
    asm("{ .reg .u64 t; cvta.to.shared.u64 t, %1; cvt.u32.u64 %0, t; }" : "=r"(a) : "l"(p));
    return a;
}
__device__ __forceinline__ void ldsm4(uint32_t* r, uint32_t addr) {
    asm volatile("ldmatrix.sync.aligned.m8n8.x4.shared.b16 {%0,%1,%2,%3}, [%4];"
                 : "=r"(r[0]), "=r"(r[1]), "=r"(r[2]), "=r"(r[3]) : "r"(addr));
}
__device__ __forceinline__ void ldsm4t(uint32_t* r, uint32_t addr) {
    asm volatile("ldmatrix.sync.aligned.m8n8.x4.trans.shared.b16 {%0,%1,%2,%3}, [%4];"
                 : "=r"(r[0]), "=r"(r[1]), "=r"(r[2]), "=r"(r[3]) : "r"(addr));
}
__device__ __forceinline__ void mma16816(float* c, const uint32_t* a,
                                         uint32_t b0, uint32_t b1) {
    asm volatile(
        "mma.sync.aligned.m16n8k16.row.col.f32.f16.f16.f32 "
        "{%0,%1,%2,%3}, {%4,%5,%6,%7}, {%8,%9}, {%0,%1,%2,%3};"
        : "+f"(c[0]), "+f"(c[1]), "+f"(c[2]), "+f"(c[3])
        : "r"(a[0]), "r"(a[1]), "r"(a[2]), "r"(a[3]), "r"(b0), "r"(b1));
}
// exact fp32 -> fp16 hi/lo split of a pair, packed as half2 words
__device__ __forceinline__ void split2(float x, float y, uint32_t& h, uint32_t& l) {
    __half hx = __float2half_rn(x), hy = __float2half_rn(y);
    __half2 H = __halves2half2(hx, hy);
    __half2 L = __halves2half2(__float2half_rn(x - __half2float(hx)),
                               __float2half_rn(y - __half2float(hy)));
    h = *(uint32_t*)&H;
    l = *(uint32_t*)&L;
}

// ---------------- weight B-fragments in canonical m16n8k16 lane layout ----------
// index: (((c*4 + nbi)*8 + kk)*2 + g)*32 + lane   (one uint4 = regs b0,b1,b2,b3)
__device__ uint4 g_wfragQKV[3 * 4 * 8 * 2 * 32];   // 6144 * 16 B = 96 KB
__device__ uint4 g_wfragP[4 * 8 * 2 * 32];         // 2048 * 16 B = 32 KB

__global__ void init_weights_kernel(const float* __restrict__ wqkv,
                                    const float* __restrict__ wproj) {
    int t = blockIdx.x * blockDim.x + threadIdx.x;   // 8192 threads
    bool isP = t >= 6144;
    int e = isP ? t - 6144 : t;
    int lane = e & 31, g = (e >> 5) & 1, kk = (e >> 6) & 7, nbi = (e >> 9) & 3;
    int c = isP ? 0 : (e >> 11);
    int gid = lane >> 2, tig = lane & 3;
    int n_a = nbi * 32 + g * 16 + gid;   // n for b0/b1
    int n_b = n_a + 8;                   // n for b2/b3
    int k0 = kk * 16 + 2 * tig;          // b0 covers k0,k0+1; b1 covers k0+8,k0+9
    float w00, w01, w10, w11, w20, w21, w30, w31;
    if (isP) {
        w00 = wproj[k0 * 128 + n_a];       w01 = wproj[(k0 + 1) * 128 + n_a];
        w10 = wproj[(k0 + 8) * 128 + n_a]; w11 = wproj[(k0 + 9) * 128 + n_a];
        w20 = wproj[k0 * 128 + n_b];       w21 = wproj[(k0 + 1) * 128 + n_b];
        w30 = wproj[(k0 + 8) * 128 + n_b]; w31 = wproj[(k0 + 9) * 128 + n_b];
    } else {
        int nb0 = c * 128;
        w00 = wqkv[k0 * 384 + nb0 + n_a];       w01 = wqkv[(k0 + 1) * 384 + nb0 + n_a];
        w10 = wqkv[(k0 + 8) * 384 + nb0 + n_a]; w11 = wqkv[(k0 + 9) * 384 + nb0 + n_a];
        w20 = wqkv[k0 * 384 + nb0 + n_b];       w21 = wqkv[(k0 + 1) * 384 + nb0 + n_b];
        w30 = wqkv[(k0 + 8) * 384 + nb0 + n_b]; w31 = wqkv[(k0 + 9) * 384 + nb0 + n_b];
    }
    __half2 r0 = __halves2half2(__float2half_rn(w00), __float2half_rn(w01));
    __half2 r1 = __halves2half2(__float2half_rn(w10), __float2half_rn(w11));
    __half2 r2 = __halves2half2(__float2half_rn(w20), __float2half_rn(w21));
    __half2 r3 = __halves2half2(__float2half_rn(w30), __float2half_rn(w31));
    uint4 v;
    v.x = *(uint32_t*)&r0; v.y = *(uint32_t*)&r1;
    v.z = *(uint32_t*)&r2; v.w = *(uint32_t*)&r3;
    (isP ? g_wfragP : g_wfragQKV)[e] = v;
}

// ---------------- main kernel: 1 window per CTA, 512 threads ----------------
__global__ __launch_bounds__(512, 1)
void swin_mma_kernel(const float* __restrict__ x,
                     const float* __restrict__ bproj,
                     float* __restrict__ out) {
    extern __shared__ char smem[];
    const uint32_t sb = smem_u32(smem);
    const int tid  = threadIdx.x;
    const int wid  = tid >> 5;
    const int lane = tid & 31;

    const int bid = blockIdx.x;
    const int b   = bid >> 10;
    const int wh  = (bid >> 5) & 31;
    const int ww  = bid & 31;

    // gather/scatter mapping
    const int l8   = tid & 63;
    const int rr   = l8 >> 3, cc8 = l8 & 7;
    const int cpar = tid >> 6;                 // 0..7
    const int gh   = (wh * 8 + rr + 4) & 255;
    const int gw   = (ww * 8 + cc8 + 4) & 255;
    const size_t gbase = (size_t)b * (128u * 65536u) + (size_t)gh * 256 + (size_t)gw;

    __half* Ah = (__half*)(smem + SA_H);
    __half* Al = (__half*)(smem + SA_L);

    // ---- Phase 1: gather + fp32 -> fp16 hi/lo (exact) split into A tile ----
    #pragma unroll 4
    for (int it = 0; it < 16; ++it) {
        int ch = cpar + it * 8;
        float v = x[gbase + (size_t)ch * 65536u];
        __half h = __float2half_rn(v);
        Ah[l8 * STRA + ch] = h;
        Al[l8 * STRA + ch] = __float2half_rn(v - __half2float(h));
    }
    __syncthreads();

    // warp roles: m0 = (wid>>2)*16 rows; nbi = wid&3 -> N block / head
    const int m0  = (wid >> 2) * 16;
    const int nbi = wid & 3;
    const int nb  = nbi * 32;
    const int gid = lane >> 2, tig = lane & 3;

    const uint32_t aOffBase =
        (uint32_t)((m0 + ((lane >> 3) & 1) * 8 + (lane & 7)) * 272 + (lane >> 4) * 16);
    const uint32_t bRowOff = (uint32_t)((((lane >> 4) & 1) * 8 + (lane & 7)) * 272);
    const uint32_t bKOff   = (uint32_t)(((lane >> 3) & 1) * 16);

    // ---- Phase 2: QKV GEMM, k-outer / chunk-inner; W fragments from global ----
    float acc[3][4][4];
    #pragma unroll
    for (int c = 0; c < 3; ++c)
        #pragma unroll
        for (int j = 0; j < 4; ++j)
            #pragma unroll
            for (int q = 0; q < 4; ++q) acc[c][j][q] = 0.f;

    #pragma unroll
    for (int kk = 0; kk < 8; ++kk) {
        const uint32_t ka = kk * 32;
        uint32_t ah[4], al[4];
        ldsm4(ah, sb + SA_H + aOffBase + ka);
        ldsm4(al, sb + SA_L + aOffBase + ka);
        #pragma unroll
        for (int c = 0; c < 3; ++c) {
            const int base = (((c * 4 + nbi) * 8 + kk) * 2) * 32 + lane;
            uint4 w0 = __ldg(&g_wfragQKV[base]);
            uint4 w1 = __ldg(&g_wfragQKV[base + 32]);
            uint32_t bb[2][4] = {{w0.x, w0.y, w0.z, w0.w}, {w1.x, w1.y, w1.z, w1.w}};
            #pragma unroll
            for (int j = 0; j < 4; ++j) {
                const int g = j >> 1, e = (j & 1) * 2;
                mma16816(acc[c][j], ah, bb[g][e], bb[g][e + 1]);
                mma16816(acc[c][j], al, bb[g][e], bb[g][e + 1]);
            }
        }
    }

    // K, V: exact split to smem tiles
    #pragma unroll
    for (int c = 1; c < 3; ++c) {
        __half* Th = (__half*)(smem + (c == 1 ? SK_H : SV_H));
        __half* Tl = (__half*)(smem + (c == 1 ? SK_L : SV_L));
        #pragma unroll
        for (int j = 0; j < 4; ++j) {
            int ccol = nb + j * 8 + 2 * tig;
            uint32_t h0, l0, h1, l1;
            split2(acc[c][j][0], acc[c][j][1], h0, l0);
            split2(acc[c][j][2], acc[c][j][3], h1, l1);
            *(uint32_t*)&Th[(m0 + gid) * STRA + ccol]     = h0;
            *(uint32_t*)&Tl[(m0 + gid) * STRA + ccol]     = l0;
            *(uint32_t*)&Th[(m0 + gid + 8) * STRA + ccol] = h1;
            *(uint32_t*)&Tl[(m0 + gid + 8) * STRA + ccol] = l1;
        }
    }

    // Q: keep in registers — acc[0] IS the A-fragment (exact hi/lo split)
    uint32_t qfh[2][4], qfl[2][4];
    #pragma unroll
    for (int kk2 = 0; kk2 < 2; ++kk2) {
        split2(acc[0][2 * kk2][0],     acc[0][2 * kk2][1],     qfh[kk2][0], qfl[kk2][0]);
        split2(acc[0][2 * kk2][2],     acc[0][2 * kk2][3],     qfh[kk2][1], qfl[kk2][1]);
        split2(acc[0][2 * kk2 + 1][0], acc[0][2 * kk2 + 1][1], qfh[kk2][2], qfl[kk2][2]);
        split2(acc[0][2 * kk2 + 1][2], acc[0][2 * kk2 + 1][3], qfh[kk2][3], qfl[kk2][3]);
    }
    __syncthreads();

    // ---- Phase 3: attention. warp -> (head = nbi, rows m0..m0+15) ----
    {
        const int head = nbi;
        const int mrow = m0;

        // S = Q K^T (3-pass exact)
        float sacc[8][4];
        #pragma unroll
        for (int j = 0; j < 8; ++j)
            #pragma unroll
            for (int q = 0; q < 4; ++q) sacc[j][q] = 0.f;

        #pragma unroll
        for (int kk2 = 0; kk2 < 2; ++kk2) {
            const uint32_t ka = kk2 * 32;
            uint32_t kh[4][4], kl[4][4];
            #pragma unroll
            for (int g = 0; g < 4; ++g) {
                uint32_t ro = (uint32_t)(g * 16 * 272) + bRowOff + bKOff +
                              (uint32_t)(head * 64) + ka;
                ldsm4(kh[g], sb + SK_H + ro);
                ldsm4(kl[g], sb + SK_L + ro);
            }
            #pragma unroll
            for (int j = 0; j < 8; ++j) {
                const int g = j >> 1, e = (j & 1) * 2;
                mma16816(sacc[j], qfh[kk2], kh[g][e], kh[g][e + 1]);
                mma16816(sacc[j], qfh[kk2], kl[g][e], kl[g][e + 1]);
                mma16816(sacc[j], qfl[kk2], kh[g][e], kh[g][e + 1]);
            }
        }

        // softmax over 64 keys
        const unsigned FULL = 0xffffffffu;
        float mx0 = -1e30f, mx1 = -1e30f;
        #pragma unroll
        for (int j = 0; j < 8; ++j) {
            mx0 = fmaxf(mx0, fmaxf(sacc[j][0], sacc[j][1]));
            mx1 = fmaxf(mx1, fmaxf(sacc[j][2], sacc[j][3]));
        }
        mx0 = fmaxf(mx0, __shfl_xor_sync(FULL, mx0, 1));
        mx0 = fmaxf(mx0, __shfl_xor_sync(FULL, mx0, 2));
        mx1 = fmaxf(mx1, __shfl_xor_sync(FULL, mx1, 1));
        mx1 = fmaxf(mx1, __shfl_xor_sync(FULL, mx1, 2));
        float sum0 = 0.f, sum1 = 0.f;
        #pragma unroll
        for (int j = 0; j < 8; ++j) {
            float e0 = __expf((sacc[j][0] - mx0) * SCALE);
            float e1 = __expf((sacc[j][1] - mx0) * SCALE);
            float e2 = __expf((sacc[j][2] - mx1) * SCALE);
            float e3 = __expf((sacc[j][3] - mx1) * SCALE);
            sacc[j][0] = e0; sacc[j][1] = e1; sacc[j][2] = e2; sacc[j][3] = e3;
            sum0 += e0 + e1; sum1 += e2 + e3;
        }
        sum0 += __shfl_xor_sync(FULL, sum0, 1);
        sum0 += __shfl_xor_sync(FULL, sum0, 2);
        sum1 += __shfl_xor_sync(FULL, sum1, 1);
        sum1 += __shfl_xor_sync(FULL, sum1, 2);
        const float inv0 = 1.0f / sum0, inv1 = 1.0f / sum1;

        // O = P V (3-pass exact; P from S accumulators, V via ldmatrix.trans)
        float oacc[4][4];
        #pragma unroll
        for (int j = 0; j < 4; ++j)
            #pragma unroll
            for (int q = 0; q < 4; ++q) oacc[j][q] = 0.f;

        const uint32_t vBase =
            (uint32_t)((((lane >> 3) & 1) * 8 + (lane & 7)) * 272 +
                       (head * 32 + (lane >> 4) * 8) * 2);

        #pragma unroll
        for (int t = 0; t < 4; ++t) {
            uint32_t ph[4], pl[4];
            split2(sacc[2 * t][0],     sacc[2 * t][1],     ph[0], pl[0]);
            split2(sacc[2 * t][2],     sacc[2 * t][3],     ph[1], pl[1]);
            split2(sacc[2 * t + 1][0], sacc[2 * t + 1][1], ph[2], pl[2]);
            split2(sacc[2 * t + 1][2], sacc[2 * t + 1][3], ph[3], pl[3]);
            uint32_t vh[2][4], vl[2][4];
            #pragma unroll
            for (int g = 0; g < 2; ++g) {
                uint32_t ro = vBase + (uint32_t)(t * 16 * 272) + (uint32_t)(g * 32);
                ldsm4t(vh[g], sb + SV_H + ro);
                ldsm4t(vl[g], sb + SV_L + ro);
            }
            #pragma unroll
            for (int j = 0; j < 4; ++j) {
                const int g = j >> 1, e = (j & 1) * 2;
                mma16816(oacc[j], ph, vh[g][e], vh[g][e + 1]);
                mma16816(oacc[j], ph, vl[g][e], vl[g][e + 1]);
                mma16816(oacc[j], pl, vh[g][e], vh[g][e + 1]);
            }
        }

        // normalize + exact split into A' (overwrites dead x A-tile)
        #pragma unroll
        for (int j = 0; j < 4; ++j) {
            int ccol = head * 32 + j * 8 + 2 * tig;
            uint32_t h0, l0, h1, l1;
            split2(oacc[j][0] * inv0, oacc[j][1] * inv0, h0, l0);
            split2(oacc[j][2] * inv1, oacc[j][3] * inv1, h1, l1);
            *(uint32_t*)&Ah[(mrow + gid) * STRA + ccol]     = h0;
            *(uint32_t*)&Al[(mrow + gid) * STRA + ccol]     = l0;
            *(uint32_t*)&Ah[(mrow + gid + 8) * STRA + ccol] = h1;
            *(uint32_t*)&Al[(mrow + gid + 8) * STRA + ccol] = l1;
        }
    }
    __syncthreads();

    // ---- Phase 4: proj GEMM + bias -> PO (overlays K tile) ----
    {
        float pacc[4][4];
        #pragma unroll
        for (int j = 0; j < 4; ++j)
            #pragma unroll
            for (int q = 0; q < 4; ++q) pacc[j][q] = 0.f;

        #pragma unroll
        for (int kk = 0; kk < 8; ++kk) {
            const uint32_t ka = kk * 32;
            uint32_t ah[4], al[4];
            ldsm4(ah, sb + SA_H + aOffBase + ka);
            ldsm4(al, sb + SA_L + aOffBase + ka);
            const int base = ((nbi * 8 + kk) * 2) * 32 + lane;
            uint4 w0 = __ldg(&g_wfragP[base]);
            uint4 w1 = __ldg(&g_wfragP[base + 32]);
            uint32_t bb[2][4] = {{w0.x, w0.y, w0.z, w0.w}, {w1.x, w1.y, w1.z, w1.w}};
            #pragma unroll
            for (int j = 0; j < 4; ++j) {
                const int g = j >> 1, e = (j & 1) * 2;
                mma16816(pacc[j], ah, bb[g][e], bb[g][e + 1]);
                mma16816(pacc[j], al, bb[g][e], bb[g][e + 1]);
            }
        }
        float* PO = (float*)(smem + SPO);
        #pragma unroll
        for (int j = 0; j < 4; ++j) {
            int ccol = nb + j * 8 + 2 * tig;
            float b0 = __ldg(&bproj[ccol]), b1 = __ldg(&bproj[ccol + 1]);
            *(float2*)&PO[(m0 + gid) * STRQ + ccol] =
                make_float2(pacc[j][0] + b0, pacc[j][1] + b1);
            *(float2*)&PO[(m0 + gid + 8) * STRQ + ccol] =
                make_float2(pacc[j][2] + b0, pacc[j][3] + b1);
        }
    }
    __syncthreads();

    // ---- Phase 5: scatter ----
    {
        const float* PO = (const float*)(smem + SPO);
        #pragma unroll 4
        for (int it = 0; it < 16; ++it) {
            int ch = cpar + it * 8;
            out[gbase + (size_t)ch * 65536u] = PO[l8 * STRQ + ch];
        }
    }
}

extern "C" void kernel_launch(void* const* d_in, const int* in_sizes, int n_in,
                              void* d_out, int out_size) {
    (void)in_sizes; (void)n_in; (void)out_size;
    const float* x     = (const float*)d_in[0];
    const float* wqkv  = (const float*)d_in[1];
    const float* wproj = (const float*)d_in[2];
    const float* bproj = (const float*)d_in[3];
    float* out = (float*)d_out;

    init_weights_kernel<<<32, 256>>>(wqkv, wproj);

    cudaFuncSetAttribute(swin_mma_kernel,
                         cudaFuncAttributeMaxDynamicSharedMemorySize, SMEM_BYTES);
    swin_mma_kernel<<<8192, 512, SMEM_BYTES>>>(x, bproj, out);
}

// round 8
// speedup vs baseline: 2.1626x; 1.1022x over previous
#include <cuda_runtime.h>
#include <cuda_fp16.h>
#include <cstdint>

// ---------------- problem constants ----------------
#define SCALE 0.1767766952966369f   // 32^-0.5

// ---------------- smem layout (bytes) ----------------
#define STRA 136                     // fp16 row stride (272 B)
#define XSTR 133                     // fp32 x-stage row stride (conflict-free)
#define SA_H 0
#define SA_L 17408
#define SK   34816                   // K fp16 single tile
#define SV   52224                   // V fp16 single tile
#define SPO  34816                   // proj-out fp32 [64][132] overlays K+V
#define STRQ 132
#define SX0  69632                   // x stage buf0: 64*133*4 = 34048
#define SX1  103680
#define SMEM_BYTES 137728

#define NWIN_PER_CTA 4
#define GRID 2048

// ---------------- ptx helpers ----------------
__device__ __forceinline__ uint32_t smem_u32(const void* p) {
    uint32_t a;
    asm("{ .reg .u64 t; cvta.to.shared.u64 t, %1; cvt.u32.u64 %0, t; }" : "=r"(a) : "l"(p));
    return a;
}
__device__ __forceinline__ void ldsm4(uint32_t* r, uint32_t addr) {
    asm volatile("ldmatrix.sync.aligned.m8n8.x4.shared.b16 {%0,%1,%2,%3}, [%4];"
                 : "=r"(r[0]), "=r"(r[1]), "=r"(r[2]), "=r"(r[3]) : "r"(addr));
}
__device__ __forceinline__ void ldsm4t(uint32_t* r, uint32_t addr) {
    asm volatile("ldmatrix.sync.aligned.m8n8.x4.trans.shared.b16 {%0,%1,%2,%3}, [%4];"
                 : "=r"(r[0]), "=r"(r[1]), "=r"(r[2]), "=r"(r[3]) : "r"(addr));
}
__device__ __forceinline__ void mma16816(float* c, const uint32_t* a,
                                         uint32_t b0, uint32_t b1) {
    asm volatile(
        "mma.sync.aligned.m16n8k16.row.col.f32.f16.f16.f32 "
        "{%0,%1,%2,%3}, {%4,%5,%6,%7}, {%8,%9}, {%0,%1,%2,%3};"
        : "+f"(c[0]), "+f"(c[1]), "+f"(c[2]), "+f"(c[3])
        : "r"(a[0]), "r"(a[1]), "r"(a[2]), "r"(a[3]), "r"(b0), "r"(b1));
}
__device__ __forceinline__ void cp4(uint32_t dst, const float* src) {
    asm volatile("cp.async.ca.shared.global [%0], [%1], 4;" :: "r"(dst), "l"(src));
}
#define CP_COMMIT() asm volatile("cp.async.commit_group;" ::: "memory")
#define CP_WAIT0()  asm volatile("cp.async.wait_group 0;" ::: "memory")

// exact fp32 -> fp16 hi/lo split of a pair, packed as half2 words
__device__ __forceinline__ void split2(float x, float y, uint32_t& h, uint32_t& l) {
    __half hx = __float2half_rn(x), hy = __float2half_rn(y);
    __half2 H = __halves2half2(hx, hy);
    __half2 L = __halves2half2(__float2half_rn(x - __half2float(hx)),
                               __float2half_rn(y - __half2float(hy)));
    h = *(uint32_t*)&H;
    l = *(uint32_t*)&L;
}
__device__ __forceinline__ uint32_t pkh2(float x, float y) {
    __half2 H = __halves2half2(__float2half_rn(x), __float2half_rn(y));
    return *(uint32_t*)&H;
}

// ---------------- weight B-fragments in canonical m16n8k16 lane layout ----------
__device__ uint4 g_wfragQKV[3 * 4 * 8 * 2 * 32];   // 96 KB
__device__ uint4 g_wfragP[4 * 8 * 2 * 32];         // 32 KB

__global__ void init_weights_kernel(const float* __restrict__ wqkv,
                                    const float* __restrict__ wproj) {
    int t = blockIdx.x * blockDim.x + threadIdx.x;   // 8192 threads
    bool isP = t >= 6144;
    int e = isP ? t - 6144 : t;
    int lane = e & 31, g = (e >> 5) & 1, kk = (e >> 6) & 7, nbi = (e >> 9) & 3;
    int c = isP ? 0 : (e >> 11);
    int gid = lane >> 2, tig = lane & 3;
    int n_a = nbi * 32 + g * 16 + gid;
    int n_b = n_a + 8;
    int k0 = kk * 16 + 2 * tig;
    float w00, w01, w10, w11, w20, w21, w30, w31;
    if (isP) {
        w00 = wproj[k0 * 128 + n_a];       w01 = wproj[(k0 + 1) * 128 + n_a];
        w10 = wproj[(k0 + 8) * 128 + n_a]; w11 = wproj[(k0 + 9) * 128 + n_a];
        w20 = wproj[k0 * 128 + n_b];       w21 = wproj[(k0 + 1) * 128 + n_b];
        w30 = wproj[(k0 + 8) * 128 + n_b]; w31 = wproj[(k0 + 9) * 128 + n_b];
    } else {
        int nb0 = c * 128;
        w00 = wqkv[k0 * 384 + nb0 + n_a];       w01 = wqkv[(k0 + 1) * 384 + nb0 + n_a];
        w10 = wqkv[(k0 + 8) * 384 + nb0 + n_a]; w11 = wqkv[(k0 + 9) * 384 + nb0 + n_a];
        w20 = wqkv[k0 * 384 + nb0 + n_b];       w21 = wqkv[(k0 + 1) * 384 + nb0 + n_b];
        w30 = wqkv[(k0 + 8) * 384 + nb0 + n_b]; w31 = wqkv[(k0 + 9) * 384 + nb0 + n_b];
    }
    uint4 v;
    v.x = pkh2(w00, w01); v.y = pkh2(w10, w11);
    v.z = pkh2(w20, w21); v.w = pkh2(w30, w31);
    (isP ? g_wfragP : g_wfragQKV)[e] = v;
}

// ---------------- main kernel: 4 windows per CTA, 512 threads ----------------
__global__ __launch_bounds__(512, 1)
void swin_mma_kernel(const float* __restrict__ x,
                     const float* __restrict__ bproj,
                     float* __restrict__ out) {
    extern __shared__ char smem[];
    const uint32_t sb = smem_u32(smem);
    const int tid  = threadIdx.x;
    const int wid  = tid >> 5;
    const int lane = tid & 31;

    // per-thread gather mapping pieces (window-independent)
    const int l8   = tid & 63;
    const int rr   = l8 >> 3, cc8 = l8 & 7;
    const int cpar = tid >> 6;                 // 0..7

    __half* Ah = (__half*)(smem + SA_H);
    __half* Al = (__half*)(smem + SA_L);

    // warp roles
    const int m0  = (wid >> 2) * 16;
    const int nbi = wid & 3;
    const int nb  = nbi * 32;
    const int gid = lane >> 2, tig = lane & 3;

    const uint32_t aOffBase =
        (uint32_t)((m0 + ((lane >> 3) & 1) * 8 + (lane & 7)) * 272 + (lane >> 4) * 16);
    const uint32_t bRowOff = (uint32_t)((((lane >> 4) & 1) * 8 + (lane & 7)) * 272);
    const uint32_t bKOff   = (uint32_t)(((lane >> 3) & 1) * 16);

    // prefetch window 0
    {
        const int win = blockIdx.x * NWIN_PER_CTA;
        const int b = win >> 10, wh = (win >> 5) & 31, ww = win & 31;
        const int gh = (wh * 8 + rr + 4) & 255;
        const int gw = (ww * 8 + cc8 + 4) & 255;
        const float* src = x + (size_t)b * (128u * 65536u) + (size_t)gh * 256 + gw;
        const uint32_t dst = sb + SX0 + (uint32_t)(l8 * XSTR + cpar) * 4;
        #pragma unroll
        for (int it = 0; it < 16; ++it)
            cp4(dst + it * 32, src + (size_t)(cpar + it * 8) * 65536u);
        CP_COMMIT();
    }

    for (int i = 0; i < NWIN_PER_CTA; ++i) {
        const int win = blockIdx.x * NWIN_PER_CTA + i;
        const int b = win >> 10, wh = (win >> 5) & 31, ww = win & 31;
        const int gh = (wh * 8 + rr + 4) & 255;
        const int gw = (ww * 8 + cc8 + 4) & 255;
        const size_t gbase = (size_t)b * (128u * 65536u) + (size_t)gh * 256 + (size_t)gw;
        const uint32_t sxCur = (i & 1) ? SX1 : SX0;

        // ---- Phase 1: wait x, split fp32 -> fp16 hi/lo into A tile ----
        CP_WAIT0();
        {
            const float* XS = (const float*)(smem + sxCur);
            #pragma unroll 4
            for (int it = 0; it < 16; ++it) {
                int ch = cpar + it * 8;
                float v = XS[l8 * XSTR + ch];
                __half h = __float2half_rn(v);
                Ah[l8 * STRA + ch] = h;
                Al[l8 * STRA + ch] = __float2half_rn(v - __half2float(h));
            }
        }
        __syncthreads();

        // ---- Phase 2: QKV GEMM (k-outer, chunk-inner), W frags from global ----
        float acc[3][4][4];
        #pragma unroll
        for (int c = 0; c < 3; ++c)
            #pragma unroll
            for (int j = 0; j < 4; ++j)
                #pragma unroll
                for (int q = 0; q < 4; ++q) acc[c][j][q] = 0.f;

        #pragma unroll
        for (int kk = 0; kk < 8; ++kk) {
            const uint32_t ka = kk * 32;
            uint32_t ah[4], al[4];
            ldsm4(ah, sb + SA_H + aOffBase + ka);
            ldsm4(al, sb + SA_L + aOffBase + ka);
            #pragma unroll
            for (int c = 0; c < 3; ++c) {
                const int base = (((c * 4 + nbi) * 8 + kk) * 2) * 32 + lane;
                uint4 w0 = __ldg(&g_wfragQKV[base]);
                uint4 w1 = __ldg(&g_wfragQKV[base + 32]);
                uint32_t bb[2][4] = {{w0.x, w0.y, w0.z, w0.w}, {w1.x, w1.y, w1.z, w1.w}};
                #pragma unroll
                for (int j = 0; j < 4; ++j) {
                    const int g = j >> 1, e = (j & 1) * 2;
                    mma16816(acc[c][j], ah, bb[g][e], bb[g][e + 1]);
                    mma16816(acc[c][j], al, bb[g][e], bb[g][e + 1]);
                }
            }
        }

        // K, V: single-rounded fp16 stores (2-pass attention error budget)
        #pragma unroll
        for (int c = 1; c < 3; ++c) {
            __half* T = (__half*)(smem + (c == 1 ? SK : SV));
            #pragma unroll
            for (int j = 0; j < 4; ++j) {
                int ccol = nb + j * 8 + 2 * tig;
                *(uint32_t*)&T[(m0 + gid) * STRA + ccol]     = pkh2(acc[c][j][0], acc[c][j][1]);
                *(uint32_t*)&T[(m0 + gid + 8) * STRA + ccol] = pkh2(acc[c][j][2], acc[c][j][3]);
            }
        }

        // Q: keep in registers — exact hi/lo A-fragments
        uint32_t qfh[2][4], qfl[2][4];
        #pragma unroll
        for (int kk2 = 0; kk2 < 2; ++kk2) {
            split2(acc[0][2 * kk2][0],     acc[0][2 * kk2][1],     qfh[kk2][0], qfl[kk2][0]);
            split2(acc[0][2 * kk2][2],     acc[0][2 * kk2][3],     qfh[kk2][1], qfl[kk2][1]);
            split2(acc[0][2 * kk2 + 1][0], acc[0][2 * kk2 + 1][1], qfh[kk2][2], qfl[kk2][2]);
            split2(acc[0][2 * kk2 + 1][2], acc[0][2 * kk2 + 1][3], qfh[kk2][3], qfl[kk2][3]);
        }
        __syncthreads();

        // ---- prefetch next window's x (overlaps attention + proj) ----
        if (i + 1 < NWIN_PER_CTA) {
            const int win2 = win + 1;
            const int b2 = win2 >> 10, wh2 = (win2 >> 5) & 31, ww2 = win2 & 31;
            const int gh2 = (wh2 * 8 + rr + 4) & 255;
            const int gw2 = (ww2 * 8 + cc8 + 4) & 255;
            const float* src = x + (size_t)b2 * (128u * 65536u) + (size_t)gh2 * 256 + gw2;
            const uint32_t dst = sb + ((i & 1) ? SX0 : SX1) + (uint32_t)(l8 * XSTR + cpar) * 4;
            #pragma unroll
            for (int it = 0; it < 16; ++it)
                cp4(dst + it * 32, src + (size_t)(cpar + it * 8) * 65536u);
            CP_COMMIT();
        }

        // ---- Phase 3: attention. warp -> (head = nbi, rows m0..m0+15) ----
        {
            const int head = nbi;
            const int mrow = m0;

            // S = Q K^T (2-pass: exact Q split x single-rounded K)
            float sacc[8][4];
            #pragma unroll
            for (int j = 0; j < 8; ++j)
                #pragma unroll
                for (int q = 0; q < 4; ++q) sacc[j][q] = 0.f;

            #pragma unroll
            for (int kk2 = 0; kk2 < 2; ++kk2) {
                const uint32_t ka = kk2 * 32;
                uint32_t kh[4][4];
                #pragma unroll
                for (int g = 0; g < 4; ++g) {
                    uint32_t ro = (uint32_t)(g * 16 * 272) + bRowOff + bKOff +
                                  (uint32_t)(head * 64) + ka;
                    ldsm4(kh[g], sb + SK + ro);
                }
                #pragma unroll
                for (int j = 0; j < 8; ++j) {
                    const int g = j >> 1, e = (j & 1) * 2;
                    mma16816(sacc[j], qfh[kk2], kh[g][e], kh[g][e + 1]);
                    mma16816(sacc[j], qfl[kk2], kh[g][e], kh[g][e + 1]);
                }
            }

            // softmax over 64 keys
            const unsigned FULL = 0xffffffffu;
            float mx0 = -1e30f, mx1 = -1e30f;
            #pragma unroll
            for (int j = 0; j < 8; ++j) {
                mx0 = fmaxf(mx0, fmaxf(sacc[j][0], sacc[j][1]));
                mx1 = fmaxf(mx1, fmaxf(sacc[j][2], sacc[j][3]));
            }
            mx0 = fmaxf(mx0, __shfl_xor_sync(FULL, mx0, 1));
            mx0 = fmaxf(mx0, __shfl_xor_sync(FULL, mx0, 2));
            mx1 = fmaxf(mx1, __shfl_xor_sync(FULL, mx1, 1));
            mx1 = fmaxf(mx1, __shfl_xor_sync(FULL, mx1, 2));
            float sum0 = 0.f, sum1 = 0.f;
            #pragma unroll
            for (int j = 0; j < 8; ++j) {
                float e0 = __expf((sacc[j][0] - mx0) * SCALE);
                float e1 = __expf((sacc[j][1] - mx0) * SCALE);
                float e2 = __expf((sacc[j][2] - mx1) * SCALE);
                float e3 = __expf((sacc[j][3] - mx1) * SCALE);
                sacc[j][0] = e0; sacc[j][1] = e1; sacc[j][2] = e2; sacc[j][3] = e3;
                sum0 += e0 + e1; sum1 += e2 + e3;
            }
            sum0 += __shfl_xor_sync(FULL, sum0, 1);
            sum0 += __shfl_xor_sync(FULL, sum0, 2);
            sum1 += __shfl_xor_sync(FULL, sum1, 1);
            sum1 += __shfl_xor_sync(FULL, sum1, 2);
            const float inv0 = 1.0f / sum0, inv1 = 1.0f / sum1;

            // O = P V (2-pass: exact P split x single-rounded V via ldsm.trans)
            float oacc[4][4];
            #pragma unroll
            for (int j = 0; j < 4; ++j)
                #pragma unroll
                for (int q = 0; q < 4; ++q) oacc[j][q] = 0.f;

            const uint32_t vBase =
                (uint32_t)((((lane >> 3) & 1) * 8 + (lane & 7)) * 272 +
                           (head * 32 + (lane >> 4) * 8) * 2);

            #pragma unroll
            for (int t = 0; t < 4; ++t) {
                uint32_t ph[4], pl[4];
                split2(sacc[2 * t][0],     sacc[2 * t][1],     ph[0], pl[0]);
                split2(sacc[2 * t][2],     sacc[2 * t][3],     ph[1], pl[1]);
                split2(sacc[2 * t + 1][0], sacc[2 * t + 1][1], ph[2], pl[2]);
                split2(sacc[2 * t + 1][2], sacc[2 * t + 1][3], ph[3], pl[3]);
                uint32_t vh[2][4];
                #pragma unroll
                for (int g = 0; g < 2; ++g) {
                    uint32_t ro = vBase + (uint32_t)(t * 16 * 272) + (uint32_t)(g * 32);
                    ldsm4t(vh[g], sb + SV + ro);
                }
                #pragma unroll
                for (int j = 0; j < 4; ++j) {
                    const int g = j >> 1, e = (j & 1) * 2;
                    mma16816(oacc[j], ph, vh[g][e], vh[g][e + 1]);
                    mma16816(oacc[j], pl, vh[g][e], vh[g][e + 1]);
                }
            }

            // normalize + exact split into A' (overwrites dead x A-tile)
            #pragma unroll
            for (int j = 0; j < 4; ++j) {
                int ccol = head * 32 + j * 8 + 2 * tig;
                uint32_t h0, l0, h1, l1;
                split2(oacc[j][0] * inv0, oacc[j][1] * inv0, h0, l0);
                split2(oacc[j][2] * inv1, oacc[j][3] * inv1, h1, l1);
                *(uint32_t*)&Ah[(mrow + gid) * STRA + ccol]     = h0;
                *(uint32_t*)&Al[(mrow + gid) * STRA + ccol]     = l0;
                *(uint32_t*)&Ah[(mrow + gid + 8) * STRA + ccol] = h1;
                *(uint32_t*)&Al[(mrow + gid + 8) * STRA + ccol] = l1;
            }
        }
        __syncthreads();

        // ---- Phase 4: proj GEMM + bias -> PO (overlays K/V region) ----
        {
            float pacc[4][4];
            #pragma unroll
            for (int j = 0; j < 4; ++j)
                #pragma unroll
                for (int q = 0; q < 4; ++q) pacc[j][q] = 0.f;

            #pragma unroll
            for (int kk = 0; kk < 8; ++kk) {
                const uint32_t ka = kk * 32;
                uint32_t ah[4], al[4];
                ldsm4(ah, sb + SA_H + aOffBase + ka);
                ldsm4(al, sb + SA_L + aOffBase + ka);
                const int base = ((nbi * 8 + kk) * 2) * 32 + lane;
                uint4 w0 = __ldg(&g_wfragP[base]);
                uint4 w1 = __ldg(&g_wfragP[base + 32]);
                uint32_t bb[2][4] = {{w0.x, w0.y, w0.z, w0.w}, {w1.x, w1.y, w1.z, w1.w}};
                #pragma unroll
                for (int j = 0; j < 4; ++j) {
                    const int g = j >> 1, e = (j & 1) * 2;
                    mma16816(pacc[j], ah, bb[g][e], bb[g][e + 1]);
                    mma16816(pacc[j], al, bb[g][e], bb[g][e + 1]);
                }
            }
            float* PO = (float*)(smem + SPO);
            #pragma unroll
            for (int j = 0; j < 4; ++j) {
                int ccol = nb + j * 8 + 2 * tig;
                float b0 = __ldg(&bproj[ccol]), b1 = __ldg(&bproj[ccol + 1]);
                *(float2*)&PO[(m0 + gid) * STRQ + ccol] =
                    make_float2(pacc[j][0] + b0, pacc[j][1] + b1);
                *(float2*)&PO[(m0 + gid + 8) * STRQ + ccol] =
                    make_float2(pacc[j][2] + b0, pacc[j][3] + b1);
            }
        }
        __syncthreads();

        // ---- Phase 5: scatter ----
        {
            const float* PO = (const float*)(smem + SPO);
            #pragma unroll 4
            for (int it = 0; it < 16; ++it) {
                int ch = cpar + it * 8;
                out[gbase + (size_t)ch * 65536u] = PO[l8 * STRQ + ch];
            }
        }
        // no sync needed: next split writes A region; scatter reads PO region
    }
}

extern "C" void kernel_launch(void* const* d_in, const int* in_sizes, int n_in,
                              void* d_out, int out_size) {
    (void)in_sizes; (void)n_in; (void)out_size;
    const float* x     = (const float*)d_in[0];
    const float* wqkv  = (const float*)d_in[1];
    const float* wproj = (const float*)d_in[2];
    const float* bproj = (const float*)d_in[3];
    float* out = (float*)d_out;

    init_weights_kernel<<<32, 256>>>(wqkv, wproj);

    cudaFuncSetAttribute(swin_mma_kernel,
                         cudaFuncAttributeMaxDynamicSharedMemorySize, SMEM_BYTES);
    swin_mma_kernel<<<GRID, 512, SMEM_BYTES>>>(x, bproj, out);
}

// round 9
// speedup vs baseline: 2.3051x; 1.0659x over previous
#include <cuda_runtime.h>
#include <cuda_fp16.h>
#include <cstdint>

// ---------------- problem constants ----------------
#define SCALE 0.1767766952966369f   // 32^-0.5

// ---------------- smem layout (bytes) ----------------
#define STRA 136                     // fp16 row stride (272 B)
#define XSTR 133                     // fp32 x-stage row stride
#define SA_H 0
#define SA_L 17408
#define SK   34816                   // K fp16 tile [64][136]
#define SV   52224                   // V fp16 tile
#define SPO  34816                   // proj-out fp32 [64][132] overlays K+V
#define STRQ 132
#define SX   69632                   // single x stage: 64*133*4 = 34048
#define SMEM_BYTES 103680

#define NWIN_PER_CTA 4
#define GRID 2048

// ---------------- ptx helpers ----------------
__device__ __forceinline__ uint32_t smem_u32(const void* p) {
    uint32_t a;
    asm("{ .reg .u64 t; cvta.to.shared.u64 t, %1; cvt.u32.u64 %0, t; }" : "=r"(a) : "l"(p));
    return a;
}
__device__ __forceinline__ void ldsm4(uint32_t* r, uint32_t addr) {
    asm volatile("ldmatrix.sync.aligned.m8n8.x4.shared.b16 {%0,%1,%2,%3}, [%4];"
                 : "=r"(r[0]), "=r"(r[1]), "=r"(r[2]), "=r"(r[3]) : "r"(addr));
}
__device__ __forceinline__ void ldsm4t(uint32_t* r, uint32_t addr) {
    asm volatile("ldmatrix.sync.aligned.m8n8.x4.trans.shared.b16 {%0,%1,%2,%3}, [%4];"
                 : "=r"(r[0]), "=r"(r[1]), "=r"(r[2]), "=r"(r[3]) : "r"(addr));
}
__device__ __forceinline__ void mma16816(float* c, const uint32_t* a,
                                         uint32_t b0, uint32_t b1) {
    asm volatile(
        "mma.sync.aligned.m16n8k16.row.col.f32.f16.f16.f32 "
        "{%0,%1,%2,%3}, {%4,%5,%6,%7}, {%8,%9}, {%0,%1,%2,%3};"
        : "+f"(c[0]), "+f"(c[1]), "+f"(c[2]), "+f"(c[3])
        : "r"(a[0]), "r"(a[1]), "r"(a[2]), "r"(a[3]), "r"(b0), "r"(b1));
}
__device__ __forceinline__ void cp4(uint32_t dst, const float* src) {
    asm volatile("cp.async.ca.shared.global [%0], [%1], 4;" :: "r"(dst), "l"(src));
}
#define CP_COMMIT() asm volatile("cp.async.commit_group;" ::: "memory")
#define CP_WAIT0()  asm volatile("cp.async.wait_group 0;" ::: "memory")

__device__ __forceinline__ void split2(float x, float y, uint32_t& h, uint32_t& l) {
    __half hx = __float2half_rn(x), hy = __float2half_rn(y);
    __half2 H = __halves2half2(hx, hy);
    __half2 L = __halves2half2(__float2half_rn(x - __half2float(hx)),
                               __float2half_rn(y - __half2float(hy)));
    h = *(uint32_t*)&H;
    l = *(uint32_t*)&L;
}
__device__ __forceinline__ uint32_t pkh2(float x, float y) {
    __half2 H = __halves2half2(__float2half_rn(x), __float2half_rn(y));
    return *(uint32_t*)&H;
}

// ---------------- weight B-fragments in canonical m16n8k16 lane layout ----------
__device__ uint4 g_wfragQKV[3 * 4 * 8 * 2 * 32];   // 96 KB
__device__ uint4 g_wfragP[4 * 8 * 2 * 32];         // 32 KB

__global__ void init_weights_kernel(const float* __restrict__ wqkv,
                                    const float* __restrict__ wproj) {
    int t = blockIdx.x * blockDim.x + threadIdx.x;   // 8192 threads
    bool isP = t >= 6144;
    int e = isP ? t - 6144 : t;
    int lane = e & 31, g = (e >> 5) & 1, kk = (e >> 6) & 7, nbi = (e >> 9) & 3;
    int c = isP ? 0 : (e >> 11);
    int gid = lane >> 2, tig = lane & 3;
    int n_a = nbi * 32 + g * 16 + gid;
    int n_b = n_a + 8;
    int k0 = kk * 16 + 2 * tig;
    float w00, w01, w10, w11, w20, w21, w30, w31;
    if (isP) {
        w00 = wproj[k0 * 128 + n_a];       w01 = wproj[(k0 + 1) * 128 + n_a];
        w10 = wproj[(k0 + 8) * 128 + n_a]; w11 = wproj[(k0 + 9) * 128 + n_a];
        w20 = wproj[k0 * 128 + n_b];       w21 = wproj[(k0 + 1) * 128 + n_b];
        w30 = wproj[(k0 + 8) * 128 + n_b]; w31 = wproj[(k0 + 9) * 128 + n_b];
    } else {
        int nb0 = c * 128;
        w00 = wqkv[k0 * 384 + nb0 + n_a];       w01 = wqkv[(k0 + 1) * 384 + nb0 + n_a];
        w10 = wqkv[(k0 + 8) * 384 + nb0 + n_a]; w11 = wqkv[(k0 + 9) * 384 + nb0 + n_a];
        w20 = wqkv[k0 * 384 + nb0 + n_b];       w21 = wqkv[(k0 + 1) * 384 + nb0 + n_b];
        w30 = wqkv[(k0 + 8) * 384 + nb0 + n_b]; w31 = wqkv[(k0 + 9) * 384 + nb0 + n_b];
    }
    uint4 v;
    v.x = pkh2(w00, w01); v.y = pkh2(w10, w11);
    v.z = pkh2(w20, w21); v.w = pkh2(w30, w31);
    (isP ? g_wfragP : g_wfragQKV)[e] = v;
}

// ---------------- main kernel: 256 threads, 2 CTAs/SM, 4 windows/CTA ----------
__global__ __launch_bounds__(256, 2)
void swin_mma_kernel(const float* __restrict__ x,
                     const float* __restrict__ bproj,
                     float* __restrict__ out) {
    extern __shared__ char smem[];
    const uint32_t sb = smem_u32(smem);
    const int tid  = threadIdx.x;
    const int wid  = tid >> 5;
    const int lane = tid & 31;

    // gather/scatter mapping: 256 threads, 64 tokens x 4 channel-stripes
    const int l8   = tid & 63;
    const int rr   = l8 >> 3, cc8 = l8 & 7;
    const int cpar = tid >> 6;                 // 0..3

    __half* Ah = (__half*)(smem + SA_H);
    __half* Al = (__half*)(smem + SA_L);

    // warp roles: 2 (M) x 4 (N); warp tile 32 rows x 32 cols
    const int m0  = (wid >> 2) * 32;
    const int nbi = wid & 3;
    const int nb  = nbi * 32;
    const int gid = lane >> 2, tig = lane & 3;

    uint32_t aOff[2];
    #pragma unroll
    for (int mt = 0; mt < 2; ++mt)
        aOff[mt] = (uint32_t)((m0 + mt * 16 + ((lane >> 3) & 1) * 8 + (lane & 7)) * 272 +
                              (lane >> 4) * 16);
    const uint32_t bRowOff = (uint32_t)((((lane >> 4) & 1) * 8 + (lane & 7)) * 272);
    const uint32_t bKOff   = (uint32_t)(((lane >> 3) & 1) * 16);

    // prefetch window 0 into the single x stage
    {
        const int win = blockIdx.x * NWIN_PER_CTA;
        const int b = win >> 10, wh = (win >> 5) & 31, ww = win & 31;
        const int gh = (wh * 8 + rr + 4) & 255;
        const int gw = (ww * 8 + cc8 + 4) & 255;
        const float* src = x + (size_t)b * (128u * 65536u) + (size_t)gh * 256 + gw;
        const uint32_t dst = sb + SX + (uint32_t)(l8 * XSTR + cpar) * 4;
        #pragma unroll
        for (int it = 0; it < 32; ++it)
            cp4(dst + it * 16, src + (size_t)(cpar + it * 4) * 65536u);
        CP_COMMIT();
    }

    for (int i = 0; i < NWIN_PER_CTA; ++i) {
        const int win = blockIdx.x * NWIN_PER_CTA + i;
        const int b = win >> 10, wh = (win >> 5) & 31, ww = win & 31;
        const int gh = (wh * 8 + rr + 4) & 255;
        const int gw = (ww * 8 + cc8 + 4) & 255;
        const size_t gbase = (size_t)b * (128u * 65536u) + (size_t)gh * 256 + (size_t)gw;

        // ---- Phase 1: wait x, split fp32 -> fp16 hi/lo into A tile ----
        CP_WAIT0();
        {
            const float* XS = (const float*)(smem + SX);
            #pragma unroll 4
            for (int it = 0; it < 32; ++it) {
                int ch = cpar + it * 4;
                float v = XS[l8 * XSTR + ch];
                __half h = __float2half_rn(v);
                Ah[l8 * STRA + ch] = h;
                Al[l8 * STRA + ch] = __float2half_rn(v - __half2float(h));
            }
        }
        __syncthreads();   // A ready; X fully consumed by all threads

        // refill X with next window immediately (lands during QKV/attention)
        if (i + 1 < NWIN_PER_CTA) {
            const int win2 = win + 1;
            const int b2 = win2 >> 10, wh2 = (win2 >> 5) & 31, ww2 = win2 & 31;
            const int gh2 = (wh2 * 8 + rr + 4) & 255;
            const int gw2 = (ww2 * 8 + cc8 + 4) & 255;
            const float* src = x + (size_t)b2 * (128u * 65536u) + (size_t)gh2 * 256 + gw2;
            const uint32_t dst = sb + SX + (uint32_t)(l8 * XSTR + cpar) * 4;
            #pragma unroll
            for (int it = 0; it < 32; ++it)
                cp4(dst + it * 16, src + (size_t)(cpar + it * 4) * 65536u);
            CP_COMMIT();
        }

        // ---- Phase 2: QKV GEMM, chunk-outer (acc 32 regs), W frags from L2 ----
        uint32_t qfh[2][2][4], qfl[2][2][4];
        #pragma unroll
        for (int c = 0; c < 3; ++c) {
            float acc[2][4][4];
            #pragma unroll
            for (int mt = 0; mt < 2; ++mt)
                #pragma unroll
                for (int j = 0; j < 4; ++j)
                    #pragma unroll
                    for (int q = 0; q < 4; ++q) acc[mt][j][q] = 0.f;

            #pragma unroll
            for (int kk = 0; kk < 8; ++kk) {
                const uint32_t ka = kk * 32;
                uint32_t ah[2][4], al[2][4];
                ldsm4(ah[0], sb + SA_H + aOff[0] + ka);
                ldsm4(ah[1], sb + SA_H + aOff[1] + ka);
                ldsm4(al[0], sb + SA_L + aOff[0] + ka);
                ldsm4(al[1], sb + SA_L + aOff[1] + ka);
                const int base = (((c * 4 + nbi) * 8 + kk) * 2) * 32 + lane;
                uint4 w0 = __ldg(&g_wfragQKV[base]);
                uint4 w1 = __ldg(&g_wfragQKV[base + 32]);
                uint32_t bb[2][4] = {{w0.x, w0.y, w0.z, w0.w}, {w1.x, w1.y, w1.z, w1.w}};
                #pragma unroll
                for (int mt = 0; mt < 2; ++mt)
                    #pragma unroll
                    for (int j = 0; j < 4; ++j) {
                        const int g = j >> 1, e = (j & 1) * 2;
                        mma16816(acc[mt][j], ah[mt], bb[g][e], bb[g][e + 1]);
                        mma16816(acc[mt][j], al[mt], bb[g][e], bb[g][e + 1]);
                    }
            }

            if (c == 0) {
                // Q -> register A-fragments (exact hi/lo)
                #pragma unroll
                for (int mt = 0; mt < 2; ++mt)
                    #pragma unroll
                    for (int kk2 = 0; kk2 < 2; ++kk2) {
                        split2(acc[mt][2 * kk2][0],     acc[mt][2 * kk2][1],
                               qfh[mt][kk2][0], qfl[mt][kk2][0]);
                        split2(acc[mt][2 * kk2][2],     acc[mt][2 * kk2][3],
                               qfh[mt][kk2][1], qfl[mt][kk2][1]);
                        split2(acc[mt][2 * kk2 + 1][0], acc[mt][2 * kk2 + 1][1],
                               qfh[mt][kk2][2], qfl[mt][kk2][2]);
                        split2(acc[mt][2 * kk2 + 1][2], acc[mt][2 * kk2 + 1][3],
                               qfh[mt][kk2][3], qfl[mt][kk2][3]);
                    }
            } else {
                __half* T = (__half*)(smem + (c == 1 ? SK : SV));
                #pragma unroll
                for (int mt = 0; mt < 2; ++mt)
                    #pragma unroll
                    for (int j = 0; j < 4; ++j) {
                        int ccol = nb + j * 8 + 2 * tig;
                        *(uint32_t*)&T[(m0 + mt * 16 + gid) * STRA + ccol] =
                            pkh2(acc[mt][j][0], acc[mt][j][1]);
                        *(uint32_t*)&T[(m0 + mt * 16 + gid + 8) * STRA + ccol] =
                            pkh2(acc[mt][j][2], acc[mt][j][3]);
                    }
            }
        }
        __syncthreads();

        // ---- Phase 3: attention. warp -> (head = nbi, rows m0..m0+31) ----
        {
            const int head = nbi;

            // S = Q K^T (2-pass), per m-tile to cap live registers
            float sacc[2][8][4];
            #pragma unroll
            for (int mt = 0; mt < 2; ++mt) {
                #pragma unroll
                for (int j = 0; j < 8; ++j)
                    #pragma unroll
                    for (int q = 0; q < 4; ++q) sacc[mt][j][q] = 0.f;
                #pragma unroll
                for (int kk2 = 0; kk2 < 2; ++kk2) {
                    const uint32_t ka = kk2 * 32;
                    uint32_t kh[4][4];
                    #pragma unroll
                    for (int g = 0; g < 4; ++g) {
                        uint32_t ro = (uint32_t)(g * 16 * 272) + bRowOff + bKOff +
                                      (uint32_t)(head * 64) + ka;
                        ldsm4(kh[g], sb + SK + ro);
                    }
                    #pragma unroll
                    for (int j = 0; j < 8; ++j) {
                        const int g = j >> 1, e = (j & 1) * 2;
                        mma16816(sacc[mt][j], qfh[mt][kk2], kh[g][e], kh[g][e + 1]);
                        mma16816(sacc[mt][j], qfl[mt][kk2], kh[g][e], kh[g][e + 1]);
                    }
                }
            }

            // softmax per m-tile
            const unsigned FULL = 0xffffffffu;
            float inv0[2], inv1[2];
            #pragma unroll
            for (int mt = 0; mt < 2; ++mt) {
                float mx0 = -1e30f, mx1 = -1e30f;
                #pragma unroll
                for (int j = 0; j < 8; ++j) {
                    mx0 = fmaxf(mx0, fmaxf(sacc[mt][j][0], sacc[mt][j][1]));
                    mx1 = fmaxf(mx1, fmaxf(sacc[mt][j][2], sacc[mt][j][3]));
                }
                mx0 = fmaxf(mx0, __shfl_xor_sync(FULL, mx0, 1));
                mx0 = fmaxf(mx0, __shfl_xor_sync(FULL, mx0, 2));
                mx1 = fmaxf(mx1, __shfl_xor_sync(FULL, mx1, 1));
                mx1 = fmaxf(mx1, __shfl_xor_sync(FULL, mx1, 2));
                float sum0 = 0.f, sum1 = 0.f;
                #pragma unroll
                for (int j = 0; j < 8; ++j) {
                    float e0 = __expf((sacc[mt][j][0] - mx0) * SCALE);
                    float e1 = __expf((sacc[mt][j][1] - mx0) * SCALE);
                    float e2 = __expf((sacc[mt][j][2] - mx1) * SCALE);
                    float e3 = __expf((sacc[mt][j][3] - mx1) * SCALE);
                    sacc[mt][j][0] = e0; sacc[mt][j][1] = e1;
                    sacc[mt][j][2] = e2; sacc[mt][j][3] = e3;
                    sum0 += e0 + e1; sum1 += e2 + e3;
                }
                sum0 += __shfl_xor_sync(FULL, sum0, 1);
                sum0 += __shfl_xor_sync(FULL, sum0, 2);
                sum1 += __shfl_xor_sync(FULL, sum1, 1);
                sum1 += __shfl_xor_sync(FULL, sum1, 2);
                inv0[mt] = 1.0f / sum0;
                inv1[mt] = 1.0f / sum1;
            }

            // O = P V (2-pass)
            float oacc[2][4][4];
            #pragma unroll
            for (int mt = 0; mt < 2; ++mt)
                #pragma unroll
                for (int j = 0; j < 4; ++j)
                    #pragma unroll
                    for (int q = 0; q < 4; ++q) oacc[mt][j][q] = 0.f;

            const uint32_t vBase =
                (uint32_t)((((lane >> 3) & 1) * 8 + (lane & 7)) * 272 +
                           (head * 32 + (lane >> 4) * 8) * 2);

            #pragma unroll
            for (int t = 0; t < 4; ++t) {
                uint32_t vh[2][4];
                #pragma unroll
                for (int g = 0; g < 2; ++g) {
                    uint32_t ro = vBase + (uint32_t)(t * 16 * 272) + (uint32_t)(g * 32);
                    ldsm4t(vh[g], sb + SV + ro);
                }
                #pragma unroll
                for (int mt = 0; mt < 2; ++mt) {
                    uint32_t ph[4], pl[4];
                    split2(sacc[mt][2 * t][0],     sacc[mt][2 * t][1],     ph[0], pl[0]);
                    split2(sacc[mt][2 * t][2],     sacc[mt][2 * t][3],     ph[1], pl[1]);
                    split2(sacc[mt][2 * t + 1][0], sacc[mt][2 * t + 1][1], ph[2], pl[2]);
                    split2(sacc[mt][2 * t + 1][2], sacc[mt][2 * t + 1][3], ph[3], pl[3]);
                    #pragma unroll
                    for (int j = 0; j < 4; ++j) {
                        const int g = j >> 1, e = (j & 1) * 2;
                        mma16816(oacc[mt][j], ph, vh[g][e], vh[g][e + 1]);
                        mma16816(oacc[mt][j], pl, vh[g][e], vh[g][e + 1]);
                    }
                }
            }

            // normalize + exact split into A' (overwrites dead x A-tile)
            #pragma unroll
            for (int mt = 0; mt < 2; ++mt)
                #pragma unroll
                for (int j = 0; j < 4; ++j) {
                    int ccol = head * 32 + j * 8 + 2 * tig;
                    uint32_t h0, l0, h1, l1;
                    split2(oacc[mt][j][0] * inv0[mt], oacc[mt][j][1] * inv0[mt], h0, l0);
                    split2(oacc[mt][j][2] * inv1[mt], oacc[mt][j][3] * inv1[mt], h1, l1);
                    *(uint32_t*)&Ah[(m0 + mt * 16 + gid) * STRA + ccol]     = h0;
                    *(uint32_t*)&Al[(m0 + mt * 16 + gid) * STRA + ccol]     = l0;
                    *(uint32_t*)&Ah[(m0 + mt * 16 + gid + 8) * STRA + ccol] = h1;
                    *(uint32_t*)&Al[(m0 + mt * 16 + gid + 8) * STRA + ccol] = l1;
                }
        }
        __syncthreads();

        // ---- Phase 4: proj GEMM + bias -> PO (overlays K/V region) ----
        {
            float pacc[2][4][4];
            #pragma unroll
            for (int mt = 0; mt < 2; ++mt)
                #pragma unroll
                for (int j = 0; j < 4; ++j)
                    #pragma unroll
                    for (int q = 0; q < 4; ++q) pacc[mt][j][q] = 0.f;

            #pragma unroll
            for (int kk = 0; kk < 8; ++kk) {
                const uint32_t ka = kk * 32;
                uint32_t ah[2][4], al[2][4];
                ldsm4(ah[0], sb + SA_H + aOff[0] + ka);
                ldsm4(ah[1], sb + SA_H + aOff[1] + ka);
                ldsm4(al[0], sb + SA_L + aOff[0] + ka);
                ldsm4(al[1], sb + SA_L + aOff[1] + ka);
                const int base = ((nbi * 8 + kk) * 2) * 32 + lane;
                uint4 w0 = __ldg(&g_wfragP[base]);
                uint4 w1 = __ldg(&g_wfragP[base + 32]);
                uint32_t bb[2][4] = {{w0.x, w0.y, w0.z, w0.w}, {w1.x, w1.y, w1.z, w1.w}};
                #pragma unroll
                for (int mt = 0; mt < 2; ++mt)
                    #pragma unroll
                    for (int j = 0; j < 4; ++j) {
                        const int g = j >> 1, e = (j & 1) * 2;
                        mma16816(pacc[mt][j], ah[mt], bb[g][e], bb[g][e + 1]);
                        mma16816(pacc[mt][j], al[mt], bb[g][e], bb[g][e + 1]);
                    }
            }
            float* PO = (float*)(smem + SPO);
            #pragma unroll
            for (int mt = 0; mt < 2; ++mt)
                #pragma unroll
                for (int j = 0; j < 4; ++j) {
                    int ccol = nb + j * 8 + 2 * tig;
                    float b0 = __ldg(&bproj[ccol]), b1 = __ldg(&bproj[ccol + 1]);
                    *(float2*)&PO[(m0 + mt * 16 + gid) * STRQ + ccol] =
                        make_float2(pacc[mt][j][0] + b0, pacc[mt][j][1] + b1);
                    *(float2*)&PO[(m0 + mt * 16 + gid + 8) * STRQ + ccol] =
                        make_float2(pacc[mt][j][2] + b0, pacc[mt][j][3] + b1);
                }
        }
        __syncthreads();

        // ---- Phase 5: scatter ----
        {
            const float* PO = (const float*)(smem + SPO);
            #pragma unroll 4
            for (int it = 0; it < 32; ++it) {
                int ch = cpar + it * 4;
                out[gbase + (size_t)ch * 65536u] = PO[l8 * STRQ + ch];
            }
        }
        // no sync needed: next phase1 writes A region; scatter reads PO region
    }
}

extern "C" void kernel_launch(void* const* d_in, const int* in_sizes, int n_in,
                              void* d_out, int out_size) {
    (void)in_sizes; (void)n_in; (void)out_size;
    const float* x     = (const float*)d_in[0];
    const float* wqkv  = (const float*)d_in[1];
    const float* wproj = (const float*)d_in[2];
    const float* bproj = (const float*)d_in[3];
    float* out = (float*)d_out;

    init_weights_kernel<<<32, 256>>>(wqkv, wproj);

    cudaFuncSetAttribute(swin_mma_kernel,
                         cudaFuncAttributeMaxDynamicSharedMemorySize, SMEM_BYTES);
    swin_mma_kernel<<<GRID, 256, SMEM_BYTES>>>(x, bproj, out);
}

// round 11
// speedup vs baseline: 3.3045x; 1.4336x over previous
#include <cuda_runtime.h>
#include <cuda_fp16.h>
#include <cstdint>

// ---------------- problem constants ----------------
#define SCALE 0.1767766952966369f   // 32^-0.5

// ---------------- smem layout (bytes) ----------------
#define STRA 136                     // fp16 row stride (272 B)
#define XSTR 134                     // fp32 x-stage row stride (EVEN: float2-aligned)
#define SA_H 0                       // A tile (single fp16), 17408 B
#define SK   17408                   // K fp16 tile [64][136]
#define SV   34816                   // V fp16 tile (ends 52224)
#define SPO  17408                   // proj-out fp32 [64][132] overlays K+V
#define STRQ 132
#define SX   52224                   // x stage: 64*134*4 = 34304
#define SMEM_BYTES 86528

#define NWIN_PER_CTA 4
#define GRID 2048

// ---------------- ptx helpers ----------------
__device__ __forceinline__ uint32_t smem_u32(const void* p) {
    uint32_t a;
    asm("{ .reg .u64 t; cvta.to.shared.u64 t, %1; cvt.u32.u64 %0, t; }" : "=r"(a) : "l"(p));
    return a;
}
__device__ __forceinline__ void ldsm4(uint32_t* r, uint32_t addr) {
    asm volatile("ldmatrix.sync.aligned.m8n8.x4.shared.b16 {%0,%1,%2,%3}, [%4];"
                 : "=r"(r[0]), "=r"(r[1]), "=r"(r[2]), "=r"(r[3]) : "r"(addr));
}
__device__ __forceinline__ void ldsm4t(uint32_t* r, uint32_t addr) {
    asm volatile("ldmatrix.sync.aligned.m8n8.x4.trans.shared.b16 {%0,%1,%2,%3}, [%4];"
                 : "=r"(r[0]), "=r"(r[1]), "=r"(r[2]), "=r"(r[3]) : "r"(addr));
}
__device__ __forceinline__ void mma16816(float* c, const uint32_t* a,
                                         uint32_t b0, uint32_t b1) {
    asm volatile(
        "mma.sync.aligned.m16n8k16.row.col.f32.f16.f16.f32 "
        "{%0,%1,%2,%3}, {%4,%5,%6,%7}, {%8,%9}, {%0,%1,%2,%3};"
        : "+f"(c[0]), "+f"(c[1]), "+f"(c[2]), "+f"(c[3])
        : "r"(a[0]), "r"(a[1]), "r"(a[2]), "r"(a[3]), "r"(b0), "r"(b1));
}
__device__ __forceinline__ void cp4(uint32_t dst, const float* src) {
    asm volatile("cp.async.ca.shared.global [%0], [%1], 4;" :: "r"(dst), "l"(src));
}
#define CP_COMMIT() asm volatile("cp.async.commit_group;" ::: "memory")
#define CP_WAIT0()  asm volatile("cp.async.wait_group 0;" ::: "memory")

__device__ __forceinline__ void split2(float x, float y, uint32_t& h, uint32_t& l) {
    __half hx = __float2half_rn(x), hy = __float2half_rn(y);
    __half2 H = __halves2half2(hx, hy);
    __half2 L = __halves2half2(__float2half_rn(x - __half2float(hx)),
                               __float2half_rn(y - __half2float(hy)));
    h = *(uint32_t*)&H;
    l = *(uint32_t*)&L;
}
__device__ __forceinline__ uint32_t pkh2(float x, float y) {
    __half2 H = __halves2half2(__float2half_rn(x), __float2half_rn(y));
    return *(uint32_t*)&H;
}

// ---------------- weight B-fragments in canonical m16n8k16 lane layout ----------
__device__ uint4 g_wfragQKV[3 * 4 * 8 * 2 * 32];   // 96 KB
__device__ uint4 g_wfragP[4 * 8 * 2 * 32];         // 32 KB

__global__ void init_weights_kernel(const float* __restrict__ wqkv,
                                    const float* __restrict__ wproj) {
    int t = blockIdx.x * blockDim.x + threadIdx.x;   // 8192 threads
    bool isP = t >= 6144;
    int e = isP ? t - 6144 : t;
    int lane = e & 31, g = (e >> 5) & 1, kk = (e >> 6) & 7, nbi = (e >> 9) & 3;
    int c = isP ? 0 : (e >> 11);
    int gid = lane >> 2, tig = lane & 3;
    int n_a = nbi * 32 + g * 16 + gid;
    int n_b = n_a + 8;
    int k0 = kk * 16 + 2 * tig;
    float w00, w01, w10, w11, w20, w21, w30, w31;
    if (isP) {
        w00 = wproj[k0 * 128 + n_a];       w01 = wproj[(k0 + 1) * 128 + n_a];
        w10 = wproj[(k0 + 8) * 128 + n_a]; w11 = wproj[(k0 + 9) * 128 + n_a];
        w20 = wproj[k0 * 128 + n_b];       w21 = wproj[(k0 + 1) * 128 + n_b];
        w30 = wproj[(k0 + 8) * 128 + n_b]; w31 = wproj[(k0 + 9) * 128 + n_b];
    } else {
        int nb0 = c * 128;
        w00 = wqkv[k0 * 384 + nb0 + n_a];       w01 = wqkv[(k0 + 1) * 384 + nb0 + n_a];
        w10 = wqkv[(k0 + 8) * 384 + nb0 + n_a]; w11 = wqkv[(k0 + 9) * 384 + nb0 + n_a];
        w20 = wqkv[k0 * 384 + nb0 + n_b];       w21 = wqkv[(k0 + 1) * 384 + nb0 + n_b];
        w30 = wqkv[(k0 + 8) * 384 + nb0 + n_b]; w31 = wqkv[(k0 + 9) * 384 + nb0 + n_b];
    }
    uint4 v;
    v.x = pkh2(w00, w01); v.y = pkh2(w10, w11);
    v.z = pkh2(w20, w21); v.w = pkh2(w30, w31);
    (isP ? g_wfragP : g_wfragQKV)[e] = v;
}

// ---------------- main kernel: 256 threads, 2 CTAs/SM, 4 windows/CTA ----------
__global__ __launch_bounds__(256, 2)
void swin_mma_kernel(const float* __restrict__ x,
                     const float* __restrict__ bproj,
                     float* __restrict__ out) {
    extern __shared__ char smem[];
    const uint32_t sb = smem_u32(smem);
    const int tid  = threadIdx.x;
    const int wid  = tid >> 5;
    const int lane = tid & 31;

    // gather/scatter mapping: 64 tokens x 4 channel-blocks of 32 contiguous ch
    const int l8   = tid & 63;
    const int rr   = l8 >> 3, cc8 = l8 & 7;
    const int ch0  = (tid >> 6) * 32;          // 0,32,64,96

    __half* Ah = (__half*)(smem + SA_H);

    // warp roles: 2 (M) x 4 (N); warp tile 32 rows x 32 cols
    const int m0  = (wid >> 2) * 32;
    const int nbi = wid & 3;
    const int nb  = nbi * 32;
    const int gid = lane >> 2, tig = lane & 3;

    uint32_t aOff[2];
    #pragma unroll
    for (int mt = 0; mt < 2; ++mt)
        aOff[mt] = (uint32_t)((m0 + mt * 16 + ((lane >> 3) & 1) * 8 + (lane & 7)) * 272 +
                              (lane >> 4) * 16);
    const uint32_t bRowOff = (uint32_t)((((lane >> 4) & 1) * 8 + (lane & 7)) * 272);
    const uint32_t bKOff   = (uint32_t)(((lane >> 3) & 1) * 16);

    // prefetch window 0 into the x stage
    {
        const int win = blockIdx.x * NWIN_PER_CTA;
        const int b = win >> 10, wh = (win >> 5) & 31, ww = win & 31;
        const int gh = (wh * 8 + rr + 4) & 255;
        const int gw = (ww * 8 + cc8 + 4) & 255;
        const float* src = x + (size_t)b * (128u * 65536u) + (size_t)gh * 256 + gw
                             + (size_t)ch0 * 65536u;
        const uint32_t dst = sb + SX + (uint32_t)(l8 * XSTR + ch0) * 4;
        #pragma unroll
        for (int it = 0; it < 32; ++it)
            cp4(dst + it * 4, src + (size_t)it * 65536u);
        CP_COMMIT();
    }

    for (int i = 0; i < NWIN_PER_CTA; ++i) {
        const int win = blockIdx.x * NWIN_PER_CTA + i;
        const int b = win >> 10, wh = (win >> 5) & 31, ww = win & 31;
        const int gh = (wh * 8 + rr + 4) & 255;
        const int gw = (ww * 8 + cc8 + 4) & 255;
        const size_t gbase = (size_t)b * (128u * 65536u) + (size_t)gh * 256 + (size_t)gw;

        // ---- Phase 1: wait x, convert fp32 -> fp16 (single-rounded) A tile ----
        CP_WAIT0();
        {
            const float* XS = (const float*)(smem + SX);
            #pragma unroll 4
            for (int it = 0; it < 16; ++it) {
                int ch = ch0 + it * 2;
                float2 v = *(const float2*)&XS[l8 * XSTR + ch];
                *(uint32_t*)&Ah[l8 * STRA + ch] = pkh2(v.x, v.y);
            }
        }
        __syncthreads();   // A ready; X fully consumed

        // refill X with next window (lands during QKV/attention)
        if (i + 1 < NWIN_PER_CTA) {
            const int win2 = win + 1;
            const int b2 = win2 >> 10, wh2 = (win2 >> 5) & 31, ww2 = win2 & 31;
            const int gh2 = (wh2 * 8 + rr + 4) & 255;
            const int gw2 = (ww2 * 8 + cc8 + 4) & 255;
            const float* src = x + (size_t)b2 * (128u * 65536u) + (size_t)gh2 * 256 + gw2
                                 + (size_t)ch0 * 65536u;
            const uint32_t dst = sb + SX + (uint32_t)(l8 * XSTR + ch0) * 4;
            #pragma unroll
            for (int it = 0; it < 32; ++it)
                cp4(dst + it * 4, src + (size_t)it * 65536u);
            CP_COMMIT();
        }

        // ---- Phase 2: QKV GEMM, single-pass fp16, chunk-outer ----
        uint32_t qfh[2][2][4], qfl[2][2][4];
        #pragma unroll
        for (int c = 0; c < 3; ++c) {
            float acc[2][4][4];
            #pragma unroll
            for (int mt = 0; mt < 2; ++mt)
                #pragma unroll
                for (int j = 0; j < 4; ++j)
                    #pragma unroll
                    for (int q = 0; q < 4; ++q) acc[mt][j][q] = 0.f;

            #pragma unroll
            for (int kk = 0; kk < 8; ++kk) {
                const uint32_t ka = kk * 32;
                uint32_t ah[2][4];
                ldsm4(ah[0], sb + SA_H + aOff[0] + ka);
                ldsm4(ah[1], sb + SA_H + aOff[1] + ka);
                const int base = (((c * 4 + nbi) * 8 + kk) * 2) * 32 + lane;
                uint4 w0 = __ldg(&g_wfragQKV[base]);
                uint4 w1 = __ldg(&g_wfragQKV[base + 32]);
                uint32_t bb[2][4] = {{w0.x, w0.y, w0.z, w0.w}, {w1.x, w1.y, w1.z, w1.w}};
                #pragma unroll
                for (int mt = 0; mt < 2; ++mt)
                    #pragma unroll
                    for (int j = 0; j < 4; ++j) {
                        const int g = j >> 1, e = (j & 1) * 2;
                        mma16816(acc[mt][j], ah[mt], bb[g][e], bb[g][e + 1]);
                    }
            }

            if (c == 0) {
                // Q -> register A-fragments (exact hi/lo from fp32 acc)
                #pragma unroll
                for (int mt = 0; mt < 2; ++mt)
                    #pragma unroll
                    for (int kk2 = 0; kk2 < 2; ++kk2) {
                        split2(acc[mt][2 * kk2][0],     acc[mt][2 * kk2][1],
                               qfh[mt][kk2][0], qfl[mt][kk2][0]);
                        split2(acc[mt][2 * kk2][2],     acc[mt][2 * kk2][3],
                               qfh[mt][kk2][1], qfl[mt][kk2][1]);
                        split2(acc[mt][2 * kk2 + 1][0], acc[mt][2 * kk2 + 1][1],
                               qfh[mt][kk2][2], qfl[mt][kk2][2]);
                        split2(acc[mt][2 * kk2 + 1][2], acc[mt][2 * kk2 + 1][3],
                               qfh[mt][kk2][3], qfl[mt][kk2][3]);
                    }
            } else {
                __half* T = (__half*)(smem + (c == 1 ? SK : SV));
                #pragma unroll
                for (int mt = 0; mt < 2; ++mt)
                    #pragma unroll
                    for (int j = 0; j < 4; ++j) {
                        int ccol = nb + j * 8 + 2 * tig;
                        *(uint32_t*)&T[(m0 + mt * 16 + gid) * STRA + ccol] =
                            pkh2(acc[mt][j][0], acc[mt][j][1]);
                        *(uint32_t*)&T[(m0 + mt * 16 + gid + 8) * STRA + ccol] =
                            pkh2(acc[mt][j][2], acc[mt][j][3]);
                    }
            }
        }
        __syncthreads();

        // ---- Phase 3: attention (2-pass: exact Q/P splits, fp16 K/V) ----
        {
            const int head = nbi;

            float sacc[2][8][4];
            #pragma unroll
            for (int mt = 0; mt < 2; ++mt) {
                #pragma unroll
                for (int j = 0; j < 8; ++j)
                    #pragma unroll
                    for (int q = 0; q < 4; ++q) sacc[mt][j][q] = 0.f;
                #pragma unroll
                for (int kk2 = 0; kk2 < 2; ++kk2) {
                    const uint32_t ka = kk2 * 32;
                    uint32_t kh[4][4];
                    #pragma unroll
                    for (int g = 0; g < 4; ++g) {
                        uint32_t ro = (uint32_t)(g * 16 * 272) + bRowOff + bKOff +
                                      (uint32_t)(head * 64) + ka;
                        ldsm4(kh[g], sb + SK + ro);
                    }
                    #pragma unroll
                    for (int j = 0; j < 8; ++j) {
                        const int g = j >> 1, e = (j & 1) * 2;
                        mma16816(sacc[mt][j], qfh[mt][kk2], kh[g][e], kh[g][e + 1]);
                        mma16816(sacc[mt][j], qfl[mt][kk2], kh[g][e], kh[g][e + 1]);
                    }
                }
            }

            const unsigned FULL = 0xffffffffu;
            float inv0[2], inv1[2];
            #pragma unroll
            for (int mt = 0; mt < 2; ++mt) {
                float mx0 = -1e30f, mx1 = -1e30f;
                #pragma unroll
                for (int j = 0; j < 8; ++j) {
                    mx0 = fmaxf(mx0, fmaxf(sacc[mt][j][0], sacc[mt][j][1]));
                    mx1 = fmaxf(mx1, fmaxf(sacc[mt][j][2], sacc[mt][j][3]));
                }
                mx0 = fmaxf(mx0, __shfl_xor_sync(FULL, mx0, 1));
                mx0 = fmaxf(mx0, __shfl_xor_sync(FULL, mx0, 2));
                mx1 = fmaxf(mx1, __shfl_xor_sync(FULL, mx1, 1));
                mx1 = fmaxf(mx1, __shfl_xor_sync(FULL, mx1, 2));
                float sum0 = 0.f, sum1 = 0.f;
                #pragma unroll
                for (int j = 0; j < 8; ++j) {
                    float e0 = __expf((sacc[mt][j][0] - mx0) * SCALE);
                    float e1 = __expf((sacc[mt][j][1] - mx0) * SCALE);
                    float e2 = __expf((sacc[mt][j][2] - mx1) * SCALE);
                    float e3 = __expf((sacc[mt][j][3] - mx1) * SCALE);
                    sacc[mt][j][0] = e0; sacc[mt][j][1] = e1;
                    sacc[mt][j][2] = e2; sacc[mt][j][3] = e3;
                    sum0 += e0 + e1; sum1 += e2 + e3;
                }
                sum0 += __shfl_xor_sync(FULL, sum0, 1);
                sum0 += __shfl_xor_sync(FULL, sum0, 2);
                sum1 += __shfl_xor_sync(FULL, sum1, 1);
                sum1 += __shfl_xor_sync(FULL, sum1, 2);
                inv0[mt] = 1.0f / sum0;
                inv1[mt] = 1.0f / sum1;
            }

            float oacc[2][4][4];
            #pragma unroll
            for (int mt = 0; mt < 2; ++mt)
                #pragma unroll
                for (int j = 0; j < 4; ++j)
                    #pragma unroll
                    for (int q = 0; q < 4; ++q) oacc[mt][j][q] = 0.f;

            const uint32_t vBase =
                (uint32_t)((((lane >> 3) & 1) * 8 + (lane & 7)) * 272 +
                           (head * 32 + (lane >> 4) * 8) * 2);

            #pragma unroll
            for (int t = 0; t < 4; ++t) {
                uint32_t vh[2][4];
                #pragma unroll
                for (int g = 0; g < 2; ++g) {
                    uint32_t ro = vBase + (uint32_t)(t * 16 * 272) + (uint32_t)(g * 32);
                    ldsm4t(vh[g], sb + SV + ro);
                }
                #pragma unroll
                for (int mt = 0; mt < 2; ++mt) {
                    uint32_t ph[4], pl[4];
                    split2(sacc[mt][2 * t][0],     sacc[mt][2 * t][1],     ph[0], pl[0]);
                    split2(sacc[mt][2 * t][2],     sacc[mt][2 * t][3],     ph[1], pl[1]);
                    split2(sacc[mt][2 * t + 1][0], sacc[mt][2 * t + 1][1], ph[2], pl[2]);
                    split2(sacc[mt][2 * t + 1][2], sacc[mt][2 * t + 1][3], ph[3], pl[3]);
                    #pragma unroll
                    for (int j = 0; j < 4; ++j) {
                        const int g = j >> 1, e = (j & 1) * 2;
                        mma16816(oacc[mt][j], ph, vh[g][e], vh[g][e + 1]);
                        mma16816(oacc[mt][j], pl, vh[g][e], vh[g][e + 1]);
                    }
                }
            }

            // normalize + single-rounded fp16 into A' (overwrites x A-tile)
            #pragma unroll
            for (int mt = 0; mt < 2; ++mt)
                #pragma unroll
                for (int j = 0; j < 4; ++j) {
                    int ccol = head * 32 + j * 8 + 2 * tig;
                    *(uint32_t*)&Ah[(m0 + mt * 16 + gid) * STRA + ccol] =
                        pkh2(oacc[mt][j][0] * inv0[mt], oacc[mt][j][1] * inv0[mt]);
                    *(uint32_t*)&Ah[(m0 + mt * 16 + gid + 8) * STRA + ccol] =
                        pkh2(oacc[mt][j][2] * inv1[mt], oacc[mt][j][3] * inv1[mt]);
                }
        }
        __syncthreads();

        // ---- Phase 4: proj GEMM (single-pass) + bias -> PO (overlays K/V) ----
        {
            float pacc[2][4][4];
            #pragma unroll
            for (int mt = 0; mt < 2; ++mt)
                #pragma unroll
                for (int j = 0; j < 4; ++j)
                    #pragma unroll
                    for (int q = 0; q < 4; ++q) pacc[mt][j][q] = 0.f;

            #pragma unroll
            for (int kk = 0; kk < 8; ++kk) {
                const uint32_t ka = kk * 32;
                uint32_t ah[2][4];
                ldsm4(ah[0], sb + SA_H + aOff[0] + ka);
                ldsm4(ah[1], sb + SA_H + aOff[1] + ka);
                const int base = ((nbi * 8 + kk) * 2) * 32 + lane;
                uint4 w0 = __ldg(&g_wfragP[base]);
                uint4 w1 = __ldg(&g_wfragP[base + 32]);
                uint32_t bb[2][4] = {{w0.x, w0.y, w0.z, w0.w}, {w1.x, w1.y, w1.z, w1.w}};
                #pragma unroll
                for (int mt = 0; mt < 2; ++mt)
                    #pragma unroll
                    for (int j = 0; j < 4; ++j) {
                        const int g = j >> 1, e = (j & 1) * 2;
                        mma16816(pacc[mt][j], ah[mt], bb[g][e], bb[g][e + 1]);
                    }
            }
            float* PO = (float*)(smem + SPO);
            #pragma unroll
            for (int mt = 0; mt < 2; ++mt)
                #pragma unroll
                for (int j = 0; j < 4; ++j) {
                    int ccol = nb + j * 8 + 2 * tig;
                    float b0 = __ldg(&bproj[ccol]), b1 = __ldg(&bproj[ccol + 1]);
                    *(float2*)&PO[(m0 + mt * 16 + gid) * STRQ + ccol] =
                        make_float2(pacc[mt][j][0] + b0, pacc[mt][j][1] + b1);
                    *(float2*)&PO[(m0 + mt * 16 + gid + 8) * STRQ + ccol] =
                        make_float2(pacc[mt][j][2] + b0, pacc[mt][j][3] + b1);
                }
        }
        __syncthreads();

        // ---- Phase 5: scatter ----
        {
            const float* PO = (const float*)(smem + SPO);
            #pragma unroll 4
            for (int it = 0; it < 32; ++it) {
                int ch = ch0 + it;
                out[gbase + (size_t)ch * 65536u] = PO[l8 * STRQ + ch];
            }
        }
        // next phase1 writes Ah region; scatter reads PO region — disjoint
    }
}

extern "C" void kernel_launch(void* const* d_in, const int* in_sizes, int n_in,
                              void* d_out, int out_size) {
    (void)in_sizes; (void)n_in; (void)out_size;
    const float* x     = (const float*)d_in[0];
    const float* wqkv  = (const float*)d_in[1];
    const float* wproj = (const float*)d_in[2];
    const float* bproj = (const float*)d_in[3];
    float* out = (float*)d_out;

    init_weights_kernel<<<32, 256>>>(wqkv, wproj);

    cudaFuncSetAttribute(swin_mma_kernel,
                         cudaFuncAttributeMaxDynamicSharedMemorySize, SMEM_BYTES);
    swin_mma_kernel<<<GRID, 256, SMEM_BYTES>>>(x, bproj, out);
}

// round 12
// speedup vs baseline: 3.3532x; 1.0147x over previous
#include <cuda_runtime.h>
#include <cuda_fp16.h>
#include <cstdint>

// ---------------- problem constants ----------------
#define SCALE 0.1767766952966369f   // 32^-0.5

// ---------------- smem layout (bytes) ----------------
#define STRA 136                     // fp16 row stride (272 B)
#define XSTR 134                     // fp32 x-stage row stride (EVEN: float2-aligned)
#define SA_H 0                       // A tile (single fp16), 17408 B
#define SK   17408                   // K fp16 tile [64][136]
#define SV   34816                   // V fp16 tile (ends 52224)
#define SPO  17408                   // proj-out fp32 [64][132] overlays K+V
#define STRQ 132
#define SX   52224                   // x stage: 64*134*4 = 34304
#define SMEM_BYTES 86528

#define NWIN_PER_CTA 4
#define GRID 2048

// ---------------- ptx helpers ----------------
__device__ __forceinline__ uint32_t smem_u32(const void* p) {
    uint32_t a;
    asm("{ .reg .u64 t; cvta.to.shared.u64 t, %1; cvt.u32.u64 %0, t; }" : "=r"(a) : "l"(p));
    return a;
}
__device__ __forceinline__ void ldsm4(uint32_t* r, uint32_t addr) {
    asm volatile("ldmatrix.sync.aligned.m8n8.x4.shared.b16 {%0,%1,%2,%3}, [%4];"
                 : "=r"(r[0]), "=r"(r[1]), "=r"(r[2]), "=r"(r[3]) : "r"(addr));
}
__device__ __forceinline__ void ldsm4t(uint32_t* r, uint32_t addr) {
    asm volatile("ldmatrix.sync.aligned.m8n8.x4.trans.shared.b16 {%0,%1,%2,%3}, [%4];"
                 : "=r"(r[0]), "=r"(r[1]), "=r"(r[2]), "=r"(r[3]) : "r"(addr));
}
__device__ __forceinline__ void mma16816(float* c, const uint32_t* a,
                                         uint32_t b0, uint32_t b1) {
    asm volatile(
        "mma.sync.aligned.m16n8k16.row.col.f32.f16.f16.f32 "
        "{%0,%1,%2,%3}, {%4,%5,%6,%7}, {%8,%9}, {%0,%1,%2,%3};"
        : "+f"(c[0]), "+f"(c[1]), "+f"(c[2]), "+f"(c[3])
        : "r"(a[0]), "r"(a[1]), "r"(a[2]), "r"(a[3]), "r"(b0), "r"(b1));
}
__device__ __forceinline__ void cp4(uint32_t dst, const float* src) {
    asm volatile("cp.async.ca.shared.global [%0], [%1], 4;" :: "r"(dst), "l"(src));
}
#define CP_COMMIT() asm volatile("cp.async.commit_group;" ::: "memory")
#define CP_WAIT0()  asm volatile("cp.async.wait_group 0;" ::: "memory")

__device__ __forceinline__ uint32_t pkh2(float x, float y) {
    __half2 H = __halves2half2(__float2half_rn(x), __float2half_rn(y));
    return *(uint32_t*)&H;
}

// ---------------- weight B-fragments in canonical m16n8k16 lane layout ----------
__device__ uint4 g_wfragQKV[3 * 4 * 8 * 2 * 32];   // 96 KB
__device__ uint4 g_wfragP[4 * 8 * 2 * 32];         // 32 KB

__global__ void init_weights_kernel(const float* __restrict__ wqkv,
                                    const float* __restrict__ wproj) {
    int t = blockIdx.x * blockDim.x + threadIdx.x;   // 8192 threads
    bool isP = t >= 6144;
    int e = isP ? t - 6144 : t;
    int lane = e & 31, g = (e >> 5) & 1, kk = (e >> 6) & 7, nbi = (e >> 9) & 3;
    int c = isP ? 0 : (e >> 11);
    int gid = lane >> 2, tig = lane & 3;
    int n_a = nbi * 32 + g * 16 + gid;
    int n_b = n_a + 8;
    int k0 = kk * 16 + 2 * tig;
    float w00, w01, w10, w11, w20, w21, w30, w31;
    if (isP) {
        w00 = wproj[k0 * 128 + n_a];       w01 = wproj[(k0 + 1) * 128 + n_a];
        w10 = wproj[(k0 + 8) * 128 + n_a]; w11 = wproj[(k0 + 9) * 128 + n_a];
        w20 = wproj[k0 * 128 + n_b];       w21 = wproj[(k0 + 1) * 128 + n_b];
        w30 = wproj[(k0 + 8) * 128 + n_b]; w31 = wproj[(k0 + 9) * 128 + n_b];
    } else {
        int nb0 = c * 128;
        w00 = wqkv[k0 * 384 + nb0 + n_a];       w01 = wqkv[(k0 + 1) * 384 + nb0 + n_a];
        w10 = wqkv[(k0 + 8) * 384 + nb0 + n_a]; w11 = wqkv[(k0 + 9) * 384 + nb0 + n_a];
        w20 = wqkv[k0 * 384 + nb0 + n_b];       w21 = wqkv[(k0 + 1) * 384 + nb0 + n_b];
        w30 = wqkv[(k0 + 8) * 384 + nb0 + n_b]; w31 = wqkv[(k0 + 9) * 384 + nb0 + n_b];
    }
    uint4 v;
    v.x = pkh2(w00, w01); v.y = pkh2(w10, w11);
    v.z = pkh2(w20, w21); v.w = pkh2(w30, w31);
    (isP ? g_wfragP : g_wfragQKV)[e] = v;
}

// ---------------- main kernel: 256 threads, 2 CTAs/SM, 4 windows/CTA ----------
__global__ __launch_bounds__(256, 2)
void swin_mma_kernel(const float* __restrict__ x,
                     const float* __restrict__ bproj,
                     float* __restrict__ out) {
    extern __shared__ char smem[];
    const uint32_t sb = smem_u32(smem);
    const int tid  = threadIdx.x;
    const int wid  = tid >> 5;
    const int lane = tid & 31;

    // gather/scatter mapping: 64 tokens x 4 channel-blocks of 32 contiguous ch
    const int l8   = tid & 63;
    const int rr   = l8 >> 3, cc8 = l8 & 7;
    const int ch0  = (tid >> 6) * 32;          // 0,32,64,96

    __half* Ah = (__half*)(smem + SA_H);

    // warp roles: 2 (M) x 4 (N); warp tile 32 rows x 32 cols
    const int m0  = (wid >> 2) * 32;
    const int nbi = wid & 3;
    const int nb  = nbi * 32;
    const int gid = lane >> 2, tig = lane & 3;

    uint32_t aOff[2];
    #pragma unroll
    for (int mt = 0; mt < 2; ++mt)
        aOff[mt] = (uint32_t)((m0 + mt * 16 + ((lane >> 3) & 1) * 8 + (lane & 7)) * 272 +
                              (lane >> 4) * 16);
    const uint32_t bRowOff = (uint32_t)((((lane >> 4) & 1) * 8 + (lane & 7)) * 272);
    const uint32_t bKOff   = (uint32_t)(((lane >> 3) & 1) * 16);

    // prefetch window 0 into the x stage
    {
        const int win = blockIdx.x * NWIN_PER_CTA;
        const int b = win >> 10, wh = (win >> 5) & 31, ww = win & 31;
        const int gh = (wh * 8 + rr + 4) & 255;
        const int gw = (ww * 8 + cc8 + 4) & 255;
        const float* src = x + (size_t)b * (128u * 65536u) + (size_t)gh * 256 + gw
                             + (size_t)ch0 * 65536u;
        const uint32_t dst = sb + SX + (uint32_t)(l8 * XSTR + ch0) * 4;
        #pragma unroll
        for (int it = 0; it < 32; ++it)
            cp4(dst + it * 4, src + (size_t)it * 65536u);
        CP_COMMIT();
    }

    for (int i = 0; i < NWIN_PER_CTA; ++i) {
        const int win = blockIdx.x * NWIN_PER_CTA + i;
        const int b = win >> 10, wh = (win >> 5) & 31, ww = win & 31;
        const int gh = (wh * 8 + rr + 4) & 255;
        const int gw = (ww * 8 + cc8 + 4) & 255;
        const size_t gbase = (size_t)b * (128u * 65536u) + (size_t)gh * 256 + (size_t)gw;

        // ---- Phase 1: wait x, convert fp32 -> fp16 (single-rounded) A tile ----
        CP_WAIT0();
        {
            const float* XS = (const float*)(smem + SX);
            #pragma unroll 4
            for (int it = 0; it < 16; ++it) {
                int ch = ch0 + it * 2;
                float2 v = *(const float2*)&XS[l8 * XSTR + ch];
                *(uint32_t*)&Ah[l8 * STRA + ch] = pkh2(v.x, v.y);
            }
        }
        __syncthreads();   // A ready; X fully consumed

        // refill X with next window (lands during QKV/attention)
        if (i + 1 < NWIN_PER_CTA) {
            const int win2 = win + 1;
            const int b2 = win2 >> 10, wh2 = (win2 >> 5) & 31, ww2 = win2 & 31;
            const int gh2 = (wh2 * 8 + rr + 4) & 255;
            const int gw2 = (ww2 * 8 + cc8 + 4) & 255;
            const float* src = x + (size_t)b2 * (128u * 65536u) + (size_t)gh2 * 256 + gw2
                                 + (size_t)ch0 * 65536u;
            const uint32_t dst = sb + SX + (uint32_t)(l8 * XSTR + ch0) * 4;
            #pragma unroll
            for (int it = 0; it < 32; ++it)
                cp4(dst + it * 4, src + (size_t)it * 65536u);
            CP_COMMIT();
        }

        // ---- Phase 2a: Q+K GEMM, kk-outer (A fragments loaded once) ----
        uint32_t qf[2][2][4];   // fp16 Q A-fragments
        {
            float accA[2][2][4][4];   // [c: Q,K][mt][j][q]
            #pragma unroll
            for (int c = 0; c < 2; ++c)
                #pragma unroll
                for (int mt = 0; mt < 2; ++mt)
                    #pragma unroll
                    for (int j = 0; j < 4; ++j)
                        #pragma unroll
                        for (int q = 0; q < 4; ++q) accA[c][mt][j][q] = 0.f;

            #pragma unroll
            for (int kk = 0; kk < 8; ++kk) {
                const uint32_t ka = kk * 32;
                uint32_t ah[2][4];
                ldsm4(ah[0], sb + SA_H + aOff[0] + ka);
                ldsm4(ah[1], sb + SA_H + aOff[1] + ka);
                #pragma unroll
                for (int c = 0; c < 2; ++c) {
                    const int base = (((c * 4 + nbi) * 8 + kk) * 2) * 32 + lane;
                    uint4 w0 = __ldg(&g_wfragQKV[base]);
                    uint4 w1 = __ldg(&g_wfragQKV[base + 32]);
                    uint32_t bb[2][4] = {{w0.x, w0.y, w0.z, w0.w},
                                         {w1.x, w1.y, w1.z, w1.w}};
                    #pragma unroll
                    for (int mt = 0; mt < 2; ++mt)
                        #pragma unroll
                        for (int j = 0; j < 4; ++j) {
                            const int g = j >> 1, e = (j & 1) * 2;
                            mma16816(accA[c][mt][j], ah[mt], bb[g][e], bb[g][e + 1]);
                        }
                }
            }

            // Q -> fp16 A-fragments (single-rounded, 1-pass attention)
            #pragma unroll
            for (int mt = 0; mt < 2; ++mt)
                #pragma unroll
                for (int kk2 = 0; kk2 < 2; ++kk2) {
                    qf[mt][kk2][0] = pkh2(accA[0][mt][2 * kk2][0],     accA[0][mt][2 * kk2][1]);
                    qf[mt][kk2][1] = pkh2(accA[0][mt][2 * kk2][2],     accA[0][mt][2 * kk2][3]);
                    qf[mt][kk2][2] = pkh2(accA[0][mt][2 * kk2 + 1][0], accA[0][mt][2 * kk2 + 1][1]);
                    qf[mt][kk2][3] = pkh2(accA[0][mt][2 * kk2 + 1][2], accA[0][mt][2 * kk2 + 1][3]);
                }

            // K -> smem (single-rounded fp16)
            __half* T = (__half*)(smem + SK);
            #pragma unroll
            for (int mt = 0; mt < 2; ++mt)
                #pragma unroll
                for (int j = 0; j < 4; ++j) {
                    int ccol = nb + j * 8 + 2 * tig;
                    *(uint32_t*)&T[(m0 + mt * 16 + gid) * STRA + ccol] =
                        pkh2(accA[1][mt][j][0], accA[1][mt][j][1]);
                    *(uint32_t*)&T[(m0 + mt * 16 + gid + 8) * STRA + ccol] =
                        pkh2(accA[1][mt][j][2], accA[1][mt][j][3]);
                }
        }

        // ---- Phase 2b: V GEMM ----
        {
            float accV[2][4][4];
            #pragma unroll
            for (int mt = 0; mt < 2; ++mt)
                #pragma unroll
                for (int j = 0; j < 4; ++j)
                    #pragma unroll
                    for (int q = 0; q < 4; ++q) accV[mt][j][q] = 0.f;

            #pragma unroll
            for (int kk = 0; kk < 8; ++kk) {
                const uint32_t ka = kk * 32;
                uint32_t ah[2][4];
                ldsm4(ah[0], sb + SA_H + aOff[0] + ka);
                ldsm4(ah[1], sb + SA_H + aOff[1] + ka);
                const int base = (((2 * 4 + nbi) * 8 + kk) * 2) * 32 + lane;
                uint4 w0 = __ldg(&g_wfragQKV[base]);
                uint4 w1 = __ldg(&g_wfragQKV[base + 32]);
                uint32_t bb[2][4] = {{w0.x, w0.y, w0.z, w0.w}, {w1.x, w1.y, w1.z, w1.w}};
                #pragma unroll
                for (int mt = 0; mt < 2; ++mt)
                    #pragma unroll
                    for (int j = 0; j < 4; ++j) {
                        const int g = j >> 1, e = (j & 1) * 2;
                        mma16816(accV[mt][j], ah[mt], bb[g][e], bb[g][e + 1]);
                    }
            }
            __half* T = (__half*)(smem + SV);
            #pragma unroll
            for (int mt = 0; mt < 2; ++mt)
                #pragma unroll
                for (int j = 0; j < 4; ++j) {
                    int ccol = nb + j * 8 + 2 * tig;
                    *(uint32_t*)&T[(m0 + mt * 16 + gid) * STRA + ccol] =
                        pkh2(accV[mt][j][0], accV[mt][j][1]);
                    *(uint32_t*)&T[(m0 + mt * 16 + gid + 8) * STRA + ccol] =
                        pkh2(accV[mt][j][2], accV[mt][j][3]);
                }
        }
        __syncthreads();

        // ---- Phase 3: attention (1-pass fp16 Q,K,P,V) ----
        {
            const int head = nbi;

            float sacc[2][8][4];
            #pragma unroll
            for (int mt = 0; mt < 2; ++mt)
                #pragma unroll
                for (int j = 0; j < 8; ++j)
                    #pragma unroll
                    for (int q = 0; q < 4; ++q) sacc[mt][j][q] = 0.f;

            #pragma unroll
            for (int kk2 = 0; kk2 < 2; ++kk2) {
                const uint32_t ka = kk2 * 32;
                uint32_t kh[4][4];
                #pragma unroll
                for (int g = 0; g < 4; ++g) {
                    uint32_t ro = (uint32_t)(g * 16 * 272) + bRowOff + bKOff +
                                  (uint32_t)(head * 64) + ka;
                    ldsm4(kh[g], sb + SK + ro);
                }
                #pragma unroll
                for (int mt = 0; mt < 2; ++mt)
                    #pragma unroll
                    for (int j = 0; j < 8; ++j) {
                        const int g = j >> 1, e = (j & 1) * 2;
                        mma16816(sacc[mt][j], qf[mt][kk2], kh[g][e], kh[g][e + 1]);
                    }
            }

            const unsigned FULL = 0xffffffffu;
            float inv0[2], inv1[2];
            #pragma unroll
            for (int mt = 0; mt < 2; ++mt) {
                float mx0 = -1e30f, mx1 = -1e30f;
                #pragma unroll
                for (int j = 0; j < 8; ++j) {
                    mx0 = fmaxf(mx0, fmaxf(sacc[mt][j][0], sacc[mt][j][1]));
                    mx1 = fmaxf(mx1, fmaxf(sacc[mt][j][2], sacc[mt][j][3]));
                }
                mx0 = fmaxf(mx0, __shfl_xor_sync(FULL, mx0, 1));
                mx0 = fmaxf(mx0, __shfl_xor_sync(FULL, mx0, 2));
                mx1 = fmaxf(mx1, __shfl_xor_sync(FULL, mx1, 1));
                mx1 = fmaxf(mx1, __shfl_xor_sync(FULL, mx1, 2));
                float sum0 = 0.f, sum1 = 0.f;
                #pragma unroll
                for (int j = 0; j < 8; ++j) {
                    float e0 = __expf((sacc[mt][j][0] - mx0) * SCALE);
                    float e1 = __expf((sacc[mt][j][1] - mx0) * SCALE);
                    float e2 = __expf((sacc[mt][j][2] - mx1) * SCALE);
                    float e3 = __expf((sacc[mt][j][3] - mx1) * SCALE);
                    sacc[mt][j][0] = e0; sacc[mt][j][1] = e1;
                    sacc[mt][j][2] = e2; sacc[mt][j][3] = e3;
                    sum0 += e0 + e1; sum1 += e2 + e3;
                }
                sum0 += __shfl_xor_sync(FULL, sum0, 1);
                sum0 += __shfl_xor_sync(FULL, sum0, 2);
                sum1 += __shfl_xor_sync(FULL, sum1, 1);
                sum1 += __shfl_xor_sync(FULL, sum1, 2);
                inv0[mt] = 1.0f / sum0;
                inv1[mt] = 1.0f / sum1;
            }

            float oacc[2][4][4];
            #pragma unroll
            for (int mt = 0; mt < 2; ++mt)
                #pragma unroll
                for (int j = 0; j < 4; ++j)
                    #pragma unroll
                    for (int q = 0; q < 4; ++q) oacc[mt][j][q] = 0.f;

            const uint32_t vBase =
                (uint32_t)((((lane >> 3) & 1) * 8 + (lane & 7)) * 272 +
                           (head * 32 + (lane >> 4) * 8) * 2);

            #pragma unroll
            for (int t = 0; t < 4; ++t) {
                uint32_t vh[2][4];
                #pragma unroll
                for (int g = 0; g < 2; ++g) {
                    uint32_t ro = vBase + (uint32_t)(t * 16 * 272) + (uint32_t)(g * 32);
                    ldsm4t(vh[g], sb + SV + ro);
                }
                #pragma unroll
                for (int mt = 0; mt < 2; ++mt) {
                    uint32_t ph[4];
                    ph[0] = pkh2(sacc[mt][2 * t][0],     sacc[mt][2 * t][1]);
                    ph[1] = pkh2(sacc[mt][2 * t][2],     sacc[mt][2 * t][3]);
                    ph[2] = pkh2(sacc[mt][2 * t + 1][0], sacc[mt][2 * t + 1][1]);
                    ph[3] = pkh2(sacc[mt][2 * t + 1][2], sacc[mt][2 * t + 1][3]);
                    #pragma unroll
                    for (int j = 0; j < 4; ++j) {
                        const int g = j >> 1, e = (j & 1) * 2;
                        mma16816(oacc[mt][j], ph, vh[g][e], vh[g][e + 1]);
                    }
                }
            }

            // normalize + single-rounded fp16 into A' (overwrites x A-tile)
            #pragma unroll
            for (int mt = 0; mt < 2; ++mt)
                #pragma unroll
                for (int j = 0; j < 4; ++j) {
                    int ccol = head * 32 + j * 8 + 2 * tig;
                    *(uint32_t*)&Ah[(m0 + mt * 16 + gid) * STRA + ccol] =
                        pkh2(oacc[mt][j][0] * inv0[mt], oacc[mt][j][1] * inv0[mt]);
                    *(uint32_t*)&Ah[(m0 + mt * 16 + gid + 8) * STRA + ccol] =
                        pkh2(oacc[mt][j][2] * inv1[mt], oacc[mt][j][3] * inv1[mt]);
                }
        }
        __syncthreads();

        // ---- Phase 4: proj GEMM (single-pass) + bias -> PO (overlays K/V) ----
        {
            float pacc[2][4][4];
            #pragma unroll
            for (int mt = 0; mt < 2; ++mt)
                #pragma unroll
                for (int j = 0; j < 4; ++j)
                    #pragma unroll
                    for (int q = 0; q < 4; ++q) pacc[mt][j][q] = 0.f;

            #pragma unroll
            for (int kk = 0; kk < 8; ++kk) {
                const uint32_t ka = kk * 32;
                uint32_t ah[2][4];
                ldsm4(ah[0], sb + SA_H + aOff[0] + ka);
                ldsm4(ah[1], sb + SA_H + aOff[1] + ka);
                const int base = ((nbi * 8 + kk) * 2) * 32 + lane;
                uint4 w0 = __ldg(&g_wfragP[base]);
                uint4 w1 = __ldg(&g_wfragP[base + 32]);
                uint32_t bb[2][4] = {{w0.x, w0.y, w0.z, w0.w}, {w1.x, w1.y, w1.z, w1.w}};
                #pragma unroll
                for (int mt = 0; mt < 2; ++mt)
                    #pragma unroll
                    for (int j = 0; j < 4; ++j) {
                        const int g = j >> 1, e = (j & 1) * 2;
                        mma16816(pacc[mt][j], ah[mt], bb[g][e], bb[g][e + 1]);
                    }
            }
            float* PO = (float*)(smem + SPO);
            #pragma unroll
            for (int mt = 0; mt < 2; ++mt)
                #pragma unroll
                for (int j = 0; j < 4; ++j) {
                    int ccol = nb + j * 8 + 2 * tig;
                    float b0 = __ldg(&bproj[ccol]), b1 = __ldg(&bproj[ccol + 1]);
                    *(float2*)&PO[(m0 + mt * 16 + gid) * STRQ + ccol] =
                        make_float2(pacc[mt][j][0] + b0, pacc[mt][j][1] + b1);
                    *(float2*)&PO[(m0 + mt * 16 + gid + 8) * STRQ + ccol] =
                        make_float2(pacc[mt][j][2] + b0, pacc[mt][j][3] + b1);
                }
        }
        __syncthreads();

        // ---- Phase 5: scatter ----
        {
            const float* PO = (const float*)(smem + SPO);
            #pragma unroll 4
            for (int it = 0; it < 32; ++it) {
                int ch = ch0 + it;
                out[gbase + (size_t)ch * 65536u] = PO[l8 * STRQ + ch];
            }
        }
        // next phase1 writes Ah region; scatter reads PO region — disjoint
    }
}

extern "C" void kernel_launch(void* const* d_in, const int* in_sizes, int n_in,
                              void* d_out, int out_size) {
    (void)in_sizes; (void)n_in; (void)out_size;
    const float* x     = (const float*)d_in[0];
    const float* wqkv  = (const float*)d_in[1];
    const float* wproj = (const float*)d_in[2];
    const float* bproj = (const float*)d_in[3];
    float* out = (float*)d_out;

    init_weights_kernel<<<32, 256>>>(wqkv, wproj);

    cudaFuncSetAttribute(swin_mma_kernel,
                         cudaFuncAttributeMaxDynamicSharedMemorySize, SMEM_BYTES);
    swin_mma_kernel<<<GRID, 256, SMEM_BYTES>>>(x, bproj, out);
}